// round 15
// baseline (speedup 1.0000x reference)
#include <cuda_runtime.h>
#include <cuda_bf16.h>
#include <math.h>
#include <stdint.h>

#define NN   131072
#define EE   262144
#define BBG  4096
#define HIDD 256
#define LLAY 4

// ---------------- scratch (device globals; no allocation) ----------------
__device__ float g_h[(size_t)NN * HIDD];                 // fp32 node states
__device__ __nv_bfloat16 g_hhi[(size_t)NN * HIDD];       // bf16 split of h
__device__ __nv_bfloat16 g_hlo[(size_t)NN * HIDD];
__device__ __nv_bfloat16 g_ehi[(size_t)EE * HIDD];       // bf16 split of e
__device__ __nv_bfloat16 g_elo[(size_t)EE * HIDD];
__device__ float g_agg[(size_t)NN * HIDD];
__device__ float g_t[(size_t)NN * HIDD];
__device__ float g_gout[(size_t)BBG * 512];
__device__ int   g_starts[BBG + 1];
// weights packed in mma.m16n8k16 B-fragment order:
// [m(12)][kb(16)][nb(16)][lane(32)] x uint4
__device__ uint4 g_wPkHi[12 * 16 * 16 * 32];
__device__ uint4 g_wPkLo[12 * 16 * 16 * 32];

// ---------------- PTX helpers ----------------
__device__ __forceinline__ uint32_t smem_u32(const void* p) {
    uint32_t a;
    asm("{ .reg .u64 t; cvta.to.shared.u64 t, %1; cvt.u32.u64 %0, t; }" : "=r"(a) : "l"(p));
    return a;
}
#define LDSM4(r0, r1, r2, r3, addr) \
    asm volatile("ldmatrix.sync.aligned.m8n8.x4.shared.b16 {%0,%1,%2,%3}, [%4];" \
        : "=r"(r0), "=r"(r1), "=r"(r2), "=r"(r3) : "r"(addr))
#define MMA_BF16(c, a0, a1, a2, a3, b0, b1) \
    asm volatile("mma.sync.aligned.m16n8k16.row.col.f32.bf16.bf16.f32 " \
        "{%0,%1,%2,%3}, {%4,%5,%6,%7}, {%8,%9}, {%0,%1,%2,%3};" \
        : "+f"((c)[0]), "+f"((c)[1]), "+f"((c)[2]), "+f"((c)[3]) \
        : "r"(a0), "r"(a1), "r"(a2), "r"(a3), "r"(b0), "r"(b1))
#define CP_ASYNC16(dst, srcp) \
    asm volatile("cp.async.cg.shared.global [%0], [%1], 16;" :: "r"(dst), "l"(srcp) : "memory")
#define CP_COMMIT() asm volatile("cp.async.commit_group;" ::: "memory")
#define CP_WAIT0()  asm volatile("cp.async.wait_group 0;" ::: "memory")
#define CP_WAIT1()  asm volatile("cp.async.wait_group 1;" ::: "memory")

// ---------------- mma.sync bf16x3 GEMM: C[M,256] = A[M,256] @ WT^T ----------------
// 128x128 C tile/CTA, 8 warps 4(m)x2(n), warp tile 32x64, 2 CTA/SM.
// AMODE 1: A pre-split bf16 hi/lo in global -> per-warp cp.async -> warp-private smem.
//          NO block barriers in mainloop (warp-private A staging, per-warp pipeline).
// AMODE 0: A fp32 -> regs -> bf16 hi/lo -> block-shared smem (barrier per chunk).
// B: pre-packed fragment-order bf16 in global via LDG.128 (L1/L2-resident, hoisted).
// EPI 0: C=relu(acc+bias)          EPI 2: C=acc
// EPI 3: agg[dst] +=RED relu(acc+bias+Tg[src])
// EPI 4: C[r]=Tg[r]+relu(acc+bias)  (residual fuse; C may alias Tg)
#define WBUF    10240   // per-warp region (AMODE1): 2 bufs x (hi 2560 + lo 2560)
#define OFF_ALO0 10240  // AMODE0: lo offset within 20480B buffer
#define MM_SMEM 81920   // AMODE1: 8*10240; epilogue staging 128*132*4=67584 aliases

template <int AMODE, int EPI>
__global__ __launch_bounds__(256, 2)
void mma_gemm(const float* __restrict__ A,
              const __nv_bfloat16* __restrict__ Ahi,
              const __nv_bfloat16* __restrict__ Alo,
              const uint4* __restrict__ WhiPk,
              const uint4* __restrict__ WloPk,
              const float* __restrict__ bias, float* __restrict__ C,
              const int* __restrict__ src, const int* __restrict__ dst,
              const float* __restrict__ Tg)
{
    extern __shared__ char dsm[];
    const uint32_t sbase = smem_u32(dsm);

    const int tid  = threadIdx.x;
    const int wid  = tid >> 5;
    const int lane = tid & 31;
    const int row0 = blockIdx.y * 128;
    const int col0 = blockIdx.x * 128;

    const int wm = wid & 3;                 // warp row (32 rows)
    const int wn = wid >> 2;                // warp col (64 cols)
    const int nb0 = (col0 >> 4) + wn * 4;   // first 16-col block for this warp

    const int lrow  = tid >> 1;             // AMODE0 loader row 0..127
    const int lhalf = tid & 1;              // AMODE0 16-float half

    float c[2][8][4];
#pragma unroll
    for (int mt = 0; mt < 2; mt++)
#pragma unroll
        for (int nt = 0; nt < 8; nt++)
#pragma unroll
            for (int q = 0; q < 4; q++) c[mt][nt][q] = 0.f;

    const uint32_t frag_r = (uint32_t)(lane & 15);
    const uint32_t frag_c = (uint32_t)((lane >> 4) << 3);

    // ---- AMODE 1: per-warp async A loader (lane owns one row of warp band) ----
    const uint32_t wbase = sbase + (uint32_t)wid * WBUF;
    auto lda_async = [&](int kc, int b) {
        uint32_t drow = wbase + b * 5120 + lane * 80;
        const char* sh = (const char*)(Ahi + (size_t)(row0 + wm * 32 + lane) * 256 + kc * 32);
        const char* sl = (const char*)(Alo + (size_t)(row0 + wm * 32 + lane) * 256 + kc * 32);
        CP_ASYNC16(drow,        sh);
        CP_ASYNC16(drow + 16,   sh + 16);
        CP_ASYNC16(drow + 32,   sh + 32);
        CP_ASYNC16(drow + 48,   sh + 48);
        CP_ASYNC16(drow + 2560,      sl);
        CP_ASYNC16(drow + 2560 + 16, sl + 16);
        CP_ASYNC16(drow + 2560 + 32, sl + 32);
        CP_ASYNC16(drow + 2560 + 48, sl + 48);
    };

    // ---- AMODE 0: block-shared convert loaders (R14 path) ----
    auto lda0 = [&](int kc, float4* va) {
        const float* ap = A + (size_t)(row0 + lrow) * 256 + kc * 32 + lhalf * 16;
        va[0] = *(const float4*)(ap + 0);
        va[1] = *(const float4*)(ap + 4);
        va[2] = *(const float4*)(ap + 8);
        va[3] = *(const float4*)(ap + 12);
    };
    auto sta0 = [&](int b, const float4* va) {
        float xs[16];
        xs[0] = va[0].x; xs[1] = va[0].y; xs[2]  = va[0].z; xs[3]  = va[0].w;
        xs[4] = va[1].x; xs[5] = va[1].y; xs[6]  = va[1].z; xs[7]  = va[1].w;
        xs[8] = va[2].x; xs[9] = va[2].y; xs[10] = va[2].z; xs[11] = va[2].w;
        xs[12] = va[3].x; xs[13] = va[3].y; xs[14] = va[3].z; xs[15] = va[3].w;
        union { __nv_bfloat16 bb[16]; uint4 u[2]; } Uh, Ul;
#pragma unroll
        for (int j = 0; j < 16; j++) {
            __nv_bfloat16 h = __float2bfloat16_rn(xs[j]);
            Uh.bb[j] = h;
            Ul.bb[j] = __float2bfloat16_rn(xs[j] - __bfloat162float(h));
        }
        char* arow = dsm + b * 20480 + lrow * 80 + lhalf * 32;
        *(uint4*)(arow)                 = Uh.u[0];
        *(uint4*)(arow + 16)            = Uh.u[1];
        *(uint4*)(arow + OFF_ALO0)      = Ul.u[0];
        *(uint4*)(arow + OFF_ALO0 + 16) = Ul.u[1];
    };

    auto compute = [&](int b, int kc) {
        const uint32_t boff    = (AMODE == 1) ? (wbase + b * 5120) : (sbase + b * 20480);
        const uint32_t loOff   = (AMODE == 1) ? 2560u : (uint32_t)OFF_ALO0;
        const uint32_t rowBase = (AMODE == 1) ? 0u : (uint32_t)(wm * 32);
#pragma unroll
        for (int ks = 0; ks < 2; ks++) {
            const int kb = kc * 2 + ks;
            // B fragments first (8 LDG.128, hoisted; latency overlaps LDSMs)
            uint4 BH[4], BL[4];
#pragma unroll
            for (int p = 0; p < 4; p++) {
                size_t bi = (size_t)((kb * 16 + nb0 + p) * 32 + lane);
                BH[p] = WhiPk[bi];
                BL[p] = WloPk[bi];
            }
            // A fragments
            const uint32_t kkb = (uint32_t)(ks * 32) + frag_c * 2;
            uint32_t ah[2][4], al[2][4];
#pragma unroll
            for (int mt = 0; mt < 2; mt++) {
                uint32_t aaddr = boff + (rowBase + mt * 16 + frag_r) * 80 + kkb;
                LDSM4(ah[mt][0], ah[mt][1], ah[mt][2], ah[mt][3], aaddr);
                LDSM4(al[mt][0], al[mt][1], al[mt][2], al[mt][3], aaddr + loOff);
            }
            // R10 ordering: per p-block, 12 MMAs grouped hi-hi / hi-lo / lo-hi
#pragma unroll
            for (int p = 0; p < 4; p++) {
                MMA_BF16(c[0][2*p],   ah[0][0], ah[0][1], ah[0][2], ah[0][3], BH[p].x, BH[p].z);
                MMA_BF16(c[0][2*p+1], ah[0][0], ah[0][1], ah[0][2], ah[0][3], BH[p].y, BH[p].w);
                MMA_BF16(c[1][2*p],   ah[1][0], ah[1][1], ah[1][2], ah[1][3], BH[p].x, BH[p].z);
                MMA_BF16(c[1][2*p+1], ah[1][0], ah[1][1], ah[1][2], ah[1][3], BH[p].y, BH[p].w);

                MMA_BF16(c[0][2*p],   ah[0][0], ah[0][1], ah[0][2], ah[0][3], BL[p].x, BL[p].z);
                MMA_BF16(c[0][2*p+1], ah[0][0], ah[0][1], ah[0][2], ah[0][3], BL[p].y, BL[p].w);
                MMA_BF16(c[1][2*p],   ah[1][0], ah[1][1], ah[1][2], ah[1][3], BL[p].x, BL[p].z);
                MMA_BF16(c[1][2*p+1], ah[1][0], ah[1][1], ah[1][2], ah[1][3], BL[p].y, BL[p].w);

                MMA_BF16(c[0][2*p],   al[0][0], al[0][1], al[0][2], al[0][3], BH[p].x, BH[p].z);
                MMA_BF16(c[0][2*p+1], al[0][0], al[0][1], al[0][2], al[0][3], BH[p].y, BH[p].w);
                MMA_BF16(c[1][2*p],   al[1][0], al[1][1], al[1][2], al[1][3], BH[p].x, BH[p].z);
                MMA_BF16(c[1][2*p+1], al[1][0], al[1][1], al[1][2], al[1][3], BH[p].y, BH[p].w);
            }
        }
    };

    // ---- mainloop ----
    if (AMODE == 1) {
        // barrier-free, per-warp pipeline
        lda_async(0, 0);
        CP_COMMIT();
        for (int kc = 0; kc < 8; kc++) {
            const int buf = kc & 1;
            if (kc < 7) {
                lda_async(kc + 1, buf ^ 1);
                CP_COMMIT();
                CP_WAIT1();      // chunk kc landed (<=1 group outstanding)
            } else {
                CP_WAIT0();
            }
            __syncwarp();
            compute(buf, kc);
        }
    } else {
        // block-synchronized convert path
        {
            float4 va0[4];
            lda0(0, va0);
            sta0(0, va0);
        }
        __syncthreads();
        for (int kc = 0; kc < 8; kc++) {
            const int buf = kc & 1;
            float4 va[4];
            if (kc < 7) lda0(kc + 1, va);
            compute(buf, kc);
            if (kc < 7) sta0(buf ^ 1, va);
            __syncthreads();
        }
    }

    // ---- stage C through smem ----
    __syncthreads();
    float* Csm = (float*)dsm;
    {
        int fr = lane >> 2;
        int fc = (lane & 3) * 2;
#pragma unroll
        for (int mt = 0; mt < 2; mt++) {
#pragma unroll
            for (int nt = 0; nt < 8; nt++) {
                int r = wm * 32 + mt * 16 + fr;
                int col = wn * 64 + nt * 8 + fc;
                *(float2*)&Csm[r * 132 + col]       = make_float2(c[mt][nt][0], c[mt][nt][1]);
                *(float2*)&Csm[(r + 8) * 132 + col] = make_float2(c[mt][nt][2], c[mt][nt][3]);
            }
        }
    }
    __syncthreads();

    // ---- final epilogue: thread handles row lrow, 64-col half ----
    {
        const int row  = lrow;
        const int coff = lhalf * 64;
        const float* crow = Csm + row * 132 + coff;
        const int grow = row0 + row;
        const int gc0  = col0 + coff;

        if (EPI == 2) {
            float* cp = C + (size_t)grow * 256 + gc0;
#pragma unroll
            for (int j = 0; j < 16; j++)
                *(float4*)(cp + 4 * j) = *(const float4*)(crow + 4 * j);
        } else if (EPI == 0) {
            float* cp = C + (size_t)grow * 256 + gc0;
            const float* bp = bias + gc0;
#pragma unroll
            for (int j = 0; j < 16; j++) {
                float4 v = *(const float4*)(crow + 4 * j);
                float4 bv = *(const float4*)(bp + 4 * j);
                float4 o;
                o.x = fmaxf(v.x + bv.x, 0.f);
                o.y = fmaxf(v.y + bv.y, 0.f);
                o.z = fmaxf(v.z + bv.z, 0.f);
                o.w = fmaxf(v.w + bv.w, 0.f);
                *(float4*)(cp + 4 * j) = o;
            }
        } else if (EPI == 4) {
            // residual fuse: C[r] = Tg[r] + relu(acc + bias); C may alias Tg
            float* cp = C + (size_t)grow * 256 + gc0;
            const float* hp = Tg + (size_t)grow * 256 + gc0;
            const float* bp = bias + gc0;
#pragma unroll
            for (int j = 0; j < 16; j++) {
                float4 v = *(const float4*)(crow + 4 * j);
                float4 hv = *(const float4*)(hp + 4 * j);
                float4 bv = *(const float4*)(bp + 4 * j);
                float4 o;
                o.x = hv.x + fmaxf(v.x + bv.x, 0.f);
                o.y = hv.y + fmaxf(v.y + bv.y, 0.f);
                o.z = hv.z + fmaxf(v.z + bv.z, 0.f);
                o.w = hv.w + fmaxf(v.w + bv.w, 0.f);
                *(float4*)(cp + 4 * j) = o;
            }
        } else { // EPI == 3
            int sr = src[grow];
            int dn = dst[grow];
            const float* tp = Tg + (size_t)sr * 256 + gc0;
            const float* bp = bias + gc0;
            float* base = C + (size_t)dn * 256 + gc0;
#pragma unroll
            for (int j = 0; j < 16; j++) {
                float4 a = *(const float4*)(crow + 4 * j);
                float4 tv = *(const float4*)(tp + 4 * j);
                float4 bv = *(const float4*)(bp + 4 * j);
                float4 v;
                v.x = fmaxf(a.x + bv.x + tv.x, 0.f);
                v.y = fmaxf(a.y + bv.y + tv.y, 0.f);
                v.z = fmaxf(a.z + bv.z + tv.z, 0.f);
                v.w = fmaxf(a.w + bv.w + tv.w, 0.f);
                atomicAdd((float4*)(base + 4 * j), v);
            }
        }
    }
}

// ---------------- weight packing into B-fragment order (once per launch) ----------------
__global__ void pack_weights(const float* __restrict__ Wm, const float* __restrict__ Wu)
{
    int idx  = blockIdx.x * 256 + threadIdx.x;    // 12*16*16*32 = 98304
    int lane = idx & 31;
    int nb   = (idx >> 5) & 15;
    int kb   = (idx >> 9) & 15;
    int m    = idx >> 13;

    const float* W = (m < 8)
        ? (Wm + (size_t)(m & 3) * 512 * 256 + (size_t)(m >> 2) * 256 * 256)
        : (Wu + (size_t)(m - 8) * 256 * 256);

    int k0 = kb * 16 + (lane & 3) * 2;
    int n0 = nb * 16 + (lane >> 2);

    union { __nv_bfloat16 b[2]; uint32_t u; } cvt;
    uint32_t ph[4], pl[4];
#pragma unroll
    for (int r = 0; r < 4; r++) {
        int kk = k0 + (r >> 1) * 8;
        int nn = n0 + (r & 1) * 8;
        float v0 = W[(size_t)kk * 256 + nn];
        float v1 = W[(size_t)(kk + 1) * 256 + nn];
        __nv_bfloat16 h0 = __float2bfloat16_rn(v0);
        __nv_bfloat16 h1 = __float2bfloat16_rn(v1);
        cvt.b[0] = h0; cvt.b[1] = h1;
        ph[r] = cvt.u;
        cvt.b[0] = __float2bfloat16_rn(v0 - __bfloat162float(h0));
        cvt.b[1] = __float2bfloat16_rn(v1 - __bfloat162float(h1));
        pl[r] = cvt.u;
    }
    g_wPkHi[idx] = make_uint4(ph[0], ph[1], ph[2], ph[3]);
    g_wPkLo[idx] = make_uint4(pl[0], pl[1], pl[2], pl[3]);
}

// ---------------- fp32 f32x2 SGEMM for ragged-K embeddings ----------------
// OUTM 1: write fp32 C AND bf16 hi/lo (for h)    OUTM 2: write bf16 hi/lo only (for e)
#define DUP2(d, f)    asm("mov.b64 %0, {%1, %1};" : "=l"(d) : "f"(f))
#define FMA2(c, a, b) asm("fma.rn.f32x2 %0, %1, %2, %0;" : "+l"(c) : "l"(a), "l"(b))
#define UNPK2(lo, hi, v) asm("mov.b64 {%0, %1}, %2;" : "=f"(lo), "=f"(hi) : "l"(v))

template <int OUTM>
__global__ __launch_bounds__(256, 2)
void gemm_emb(const float* __restrict__ A, int lda, int K,
              const float* __restrict__ Bw,
              const float* __restrict__ bias,
              float* __restrict__ C,
              __nv_bfloat16* __restrict__ Chi,
              __nv_bfloat16* __restrict__ Clo)
{
    __shared__ float As[2][8][128];
    __shared__ float Bs[2][8][128];

    const int tid  = threadIdx.x;
    const int row0 = blockIdx.y * 128;
    const int col0 = blockIdx.x * 128;

    const int aRow = tid >> 1;
    const int aCol = (tid & 1) << 2;
    const int bRow = tid >> 5;
    const int bCol = (tid & 31) << 2;

    auto load_a = [&](int kt) -> float4 {
        float t0 = 0.f, t1 = 0.f, t2 = 0.f, t3 = 0.f;
        const float* arow = A + (size_t)(row0 + aRow) * lda;
        int k0 = kt + aCol;
        if (k0 + 0 < K) t0 = arow[k0 + 0];
        if (k0 + 1 < K) t1 = arow[k0 + 1];
        if (k0 + 2 < K) t2 = arow[k0 + 2];
        if (k0 + 3 < K) t3 = arow[k0 + 3];
        return make_float4(t0, t1, t2, t3);
    };
    auto load_b = [&](int kt) -> float4 {
        int kb = kt + bRow;
        if (kb >= K) return make_float4(0.f, 0.f, 0.f, 0.f);
        return *(const float4*)(Bw + (size_t)kb * 256 + col0 + bCol);
    };
    auto store_tile = [&](int p, float4 a4, float4 b4) {
        As[p][aCol + 0][aRow] = a4.x;
        As[p][aCol + 1][aRow] = a4.y;
        As[p][aCol + 2][aRow] = a4.z;
        As[p][aCol + 3][aRow] = a4.w;
        *(float4*)&Bs[p][bRow][bCol] = b4;
    };

    unsigned long long acc2[4][8];
#pragma unroll
    for (int i2 = 0; i2 < 4; i2++)
#pragma unroll
        for (int j = 0; j < 8; j++) acc2[i2][j] = 0ULL;

    const int tx = tid & 15;
    const int ty = tid >> 4;

    auto compute = [&](int p) {
#pragma unroll
        for (int kk = 0; kk < 8; kk++) {
            ulonglong2 aA = *(const ulonglong2*)&As[p][kk][ty * 4];
            ulonglong2 aB = *(const ulonglong2*)&As[p][kk][64 + ty * 4];
            unsigned long long a2[4] = {aA.x, aA.y, aB.x, aB.y};
            float4 b0 = *(const float4*)&Bs[p][kk][tx * 4];
            float4 b1 = *(const float4*)&Bs[p][kk][64 + tx * 4];
            unsigned long long bb2[8];
            DUP2(bb2[0], b0.x); DUP2(bb2[1], b0.y); DUP2(bb2[2], b0.z); DUP2(bb2[3], b0.w);
            DUP2(bb2[4], b1.x); DUP2(bb2[5], b1.y); DUP2(bb2[6], b1.z); DUP2(bb2[7], b1.w);
#pragma unroll
            for (int i2 = 0; i2 < 4; i2++)
#pragma unroll
                for (int j = 0; j < 8; j++)
                    FMA2(acc2[i2][j], a2[i2], bb2[j]);
        }
    };

    store_tile(0, load_a(0), load_b(0));
    __syncthreads();
    int p = 0;
    for (int kt = 8; kt < K; kt += 8) {
        float4 a4 = load_a(kt);
        float4 b4 = load_b(kt);
        compute(p);
        store_tile(p ^ 1, a4, b4);
        __syncthreads();
        p ^= 1;
    }
    compute(p);

    float acc[8][8];
#pragma unroll
    for (int i2 = 0; i2 < 4; i2++)
#pragma unroll
        for (int j = 0; j < 8; j++)
            UNPK2(acc[2 * i2][j], acc[2 * i2 + 1][j], acc2[i2][j]);

    float bb[8];
#pragma unroll
    for (int j = 0; j < 4; j++) {
        bb[j]     = bias[col0 + tx * 4 + j];
        bb[4 + j] = bias[col0 + 64 + tx * 4 + j];
    }
#pragma unroll
    for (int i = 0; i < 8; i++) {
        int lrow = (i < 4) ? (ty * 4 + i) : (64 + ty * 4 + (i - 4));
        size_t base = (size_t)(row0 + lrow) * 256 + col0;
        float v[8];
#pragma unroll
        for (int j = 0; j < 8; j++) v[j] = fmaxf(acc[i][j] + bb[j], 0.f);

        if (OUTM == 1) {
            *(float4*)(C + base + tx * 4)      = make_float4(v[0], v[1], v[2], v[3]);
            *(float4*)(C + base + 64 + tx * 4) = make_float4(v[4], v[5], v[6], v[7]);
        }
        union { __nv_bfloat16 b[4]; uint2 u; } H0, H1, L0, L1;
#pragma unroll
        for (int j = 0; j < 4; j++) {
            __nv_bfloat16 h = __float2bfloat16_rn(v[j]);
            H0.b[j] = h;
            L0.b[j] = __float2bfloat16_rn(v[j] - __bfloat162float(h));
            __nv_bfloat16 h2 = __float2bfloat16_rn(v[4 + j]);
            H1.b[j] = h2;
            L1.b[j] = __float2bfloat16_rn(v[4 + j] - __bfloat162float(h2));
        }
        *(uint2*)(Chi + base + tx * 4)      = H0.u;
        *(uint2*)(Chi + base + 64 + tx * 4) = H1.u;
        *(uint2*)(Clo + base + tx * 4)      = L0.u;
        *(uint2*)(Clo + base + 64 + tx * 4) = L1.u;
    }
}

// ---------------- LayerNorm (in place) + bf16 split ----------------
__global__ void ln_kernel(const float* __restrict__ lg,
                          const float* __restrict__ lb)
{
    int row  = blockIdx.x * 8 + (threadIdx.x >> 5);
    int lane = threadIdx.x & 31;
    float* hrow = g_h + (size_t)row * 256;

    float x[8];
    float4 h0 = *(const float4*)(hrow + lane * 4);
    float4 h1 = *(const float4*)(hrow + 128 + lane * 4);
    x[0] = h0.x; x[1] = h0.y; x[2] = h0.z; x[3] = h0.w;
    x[4] = h1.x; x[5] = h1.y; x[6] = h1.z; x[7] = h1.w;

    float s = 0.f, q = 0.f;
#pragma unroll
    for (int j = 0; j < 8; j++) { s += x[j]; q += x[j] * x[j]; }
#pragma unroll
    for (int o = 16; o > 0; o >>= 1) {
        s += __shfl_xor_sync(0xFFFFFFFFu, s, o);
        q += __shfl_xor_sync(0xFFFFFFFFu, q, o);
    }
    float mu  = s * (1.f / 256.f);
    float var = q * (1.f / 256.f) - mu * mu;
    float rs  = rsqrtf(var + 1e-5f);

    float4 g0 = *(const float4*)(lg + lane * 4);
    float4 g1 = *(const float4*)(lg + 128 + lane * 4);
    float4 b0 = *(const float4*)(lb + lane * 4);
    float4 b1 = *(const float4*)(lb + 128 + lane * 4);

    float y[8];
    y[0] = (x[0] - mu) * rs * g0.x + b0.x;
    y[1] = (x[1] - mu) * rs * g0.y + b0.y;
    y[2] = (x[2] - mu) * rs * g0.z + b0.z;
    y[3] = (x[3] - mu) * rs * g0.w + b0.w;
    y[4] = (x[4] - mu) * rs * g1.x + b1.x;
    y[5] = (x[5] - mu) * rs * g1.y + b1.y;
    y[6] = (x[6] - mu) * rs * g1.z + b1.z;
    y[7] = (x[7] - mu) * rs * g1.w + b1.w;
    *(float4*)(hrow + lane * 4)       = make_float4(y[0], y[1], y[2], y[3]);
    *(float4*)(hrow + 128 + lane * 4) = make_float4(y[4], y[5], y[6], y[7]);

    union { __nv_bfloat16 b[4]; uint2 u; } H0, H1, L0, L1;
#pragma unroll
    for (int j = 0; j < 4; j++) {
        __nv_bfloat16 h = __float2bfloat16_rn(y[j]);
        H0.b[j] = h;
        L0.b[j] = __float2bfloat16_rn(y[j] - __bfloat162float(h));
        __nv_bfloat16 h2 = __float2bfloat16_rn(y[4 + j]);
        H1.b[j] = h2;
        L1.b[j] = __float2bfloat16_rn(y[4 + j] - __bfloat162float(h2));
    }
    size_t base = (size_t)row * 256;
    *(uint2*)(g_hhi + base + lane * 4)       = H0.u;
    *(uint2*)(g_hhi + base + 128 + lane * 4) = H1.u;
    *(uint2*)(g_hlo + base + lane * 4)       = L0.u;
    *(uint2*)(g_hlo + base + 128 + lane * 4) = L1.u;
}

// ---------------- segment starts from sorted b ----------------
__global__ void seg_starts(const int* __restrict__ b)
{
    int i = blockIdx.x * blockDim.x + threadIdx.x;
    if (i >= NN) return;
    int cur = b[i];
    if (i == 0) {
        for (int g = 0; g <= cur; g++) g_starts[g] = 0;
    } else {
        int prev = b[i - 1];
        if (prev != cur)
            for (int g = prev + 1; g <= cur; g++) g_starts[g] = i;
    }
    if (i == NN - 1)
        for (int g = cur + 1; g <= BBG; g++) g_starts[g] = NN;
}

// ---------------- readout: mean || max per graph ----------------
__global__ void readout_kernel(void)
{
    int g = blockIdx.x;
    int s = g_starts[g], en = g_starts[g + 1];
    int c = threadIdx.x;
    float sum = 0.f, mx = -INFINITY;
    for (int r = s; r < en; r++) {
        float v = g_h[(size_t)r * 256 + c];
        sum += v;
        mx = fmaxf(mx, v);
    }
    int   cnt   = en - s;
    float denom = (cnt > 0) ? (float)cnt : 1.f;
    g_gout[(size_t)g * 512 + c]       = sum / denom;
    g_gout[(size_t)g * 512 + 256 + c] = (cnt > 0) ? mx : 0.f;
}

// ---------------- FiLM + predictor, 8 graphs per block ----------------
__global__ __launch_bounds__(256)
void film_pred(const float* __restrict__ ctx, const int* __restrict__ pid,
               const float* __restrict__ gW1, const float* __restrict__ gb1,
               const float* __restrict__ glng, const float* __restrict__ glnb,
               const float* __restrict__ gW2, const float* __restrict__ gb2,
               const float* __restrict__ bW1, const float* __restrict__ bb1,
               const float* __restrict__ blng, const float* __restrict__ blnb,
               const float* __restrict__ bW2, const float* __restrict__ bb2,
               const float* __restrict__ pW1, const float* __restrict__ pb1,
               const float* __restrict__ pW2, const float* __restrict__ pb2,
               float* __restrict__ out)
{
    __shared__ float s_c[8][128];
    __shared__ float s_t[8][256];
    __shared__ float s_hmod[8][512];

    int tid = threadIdx.x;
    int g0  = blockIdx.x * 8;

    for (int i = tid; i < 8 * 128; i += 256) {
        int r = i >> 7, k = i & 127;
        s_c[r][k] = ctx[(size_t)pid[g0 + r] * 128 + k];
    }
    __syncthreads();

#pragma unroll
    for (int net = 0; net < 2; net++) {
        const float* W1 = net ? bW1 : gW1;
        const float* B1 = net ? bb1 : gb1;
        const float* LG = net ? blng : glng;
        const float* LB = net ? blnb : glnb;
        const float* W2 = net ? bW2 : gW2;
        const float* B2 = net ? bb2 : gb2;

        float a1[8];
#pragma unroll
        for (int r = 0; r < 8; r++) a1[r] = B1[tid];
        for (int k = 0; k < 128; k++) {
            float w = W1[k * 256 + tid];
#pragma unroll
            for (int r = 0; r < 8; r++) a1[r] += s_c[r][k] * w;
        }
#pragma unroll
        for (int r = 0; r < 8; r++) s_t[r][tid] = a1[r];
        __syncthreads();

        {
            int r = tid >> 5, lane = tid & 31;
            float x[8], s = 0.f, q = 0.f;
#pragma unroll
            for (int j = 0; j < 8; j++) {
                x[j] = s_t[r][lane + 32 * j];
                s += x[j]; q += x[j] * x[j];
            }
#pragma unroll
            for (int o = 16; o > 0; o >>= 1) {
                s += __shfl_xor_sync(0xFFFFFFFFu, s, o);
                q += __shfl_xor_sync(0xFFFFFFFFu, q, o);
            }
            float mu  = s * (1.f / 256.f);
            float var = q * (1.f / 256.f) - mu * mu;
            float rs  = rsqrtf(var + 1e-5f);
#pragma unroll
            for (int j = 0; j < 8; j++) {
                int cc = lane + 32 * j;
                float y = (x[j] - mu) * rs * LG[cc] + LB[cc];
                s_t[r][cc] = fmaxf(y, 0.f);
            }
        }
        __syncthreads();

        float a20[8], a21[8];
#pragma unroll
        for (int r = 0; r < 8; r++) { a20[r] = 0.f; a21[r] = 0.f; }
        for (int k = 0; k < 256; k++) {
            float w0 = W2[k * 512 + tid];
            float w1 = W2[k * 512 + tid + 256];
#pragma unroll
            for (int r = 0; r < 8; r++) {
                float t = s_t[r][k];
                a20[r] += t * w0;
                a21[r] += t * w1;
            }
        }
        float bc0 = B2[tid], bc1 = B2[tid + 256];
        if (net == 0) {
#pragma unroll
            for (int r = 0; r < 8; r++) {
                s_hmod[r][tid]       = (a20[r] + bc0) * g_gout[(size_t)(g0 + r) * 512 + tid];
                s_hmod[r][tid + 256] = (a21[r] + bc1) * g_gout[(size_t)(g0 + r) * 512 + tid + 256];
            }
        } else {
#pragma unroll
            for (int r = 0; r < 8; r++) {
                s_hmod[r][tid]       += a20[r] + bc0;
                s_hmod[r][tid + 256] += a21[r] + bc1;
            }
        }
        __syncthreads();
    }

    float az[8];
#pragma unroll
    for (int r = 0; r < 8; r++) az[r] = pb1[tid];
    for (int k = 0; k < 512; k++) {
        float w = pW1[k * 256 + tid];
#pragma unroll
        for (int r = 0; r < 8; r++) az[r] += s_hmod[r][k] * w;
    }
#pragma unroll
    for (int r = 0; r < 8; r++) s_t[r][tid] = fmaxf(az[r], 0.f);
    __syncthreads();

    {
        int r = tid >> 5, lane = tid & 31;
        float p = 0.f;
#pragma unroll
        for (int j = 0; j < 8; j++) {
            int cc = lane + 32 * j;
            p += s_t[r][cc] * pW2[cc];
        }
#pragma unroll
        for (int o = 16; o > 0; o >>= 1) p += __shfl_xor_sync(0xFFFFFFFFu, p, o);
        if (lane == 0) out[g0 + r] = p + pb2[0];
    }
}

// ---------------- host launcher ----------------
extern "C" void kernel_launch(void* const* d_in, const int* in_sizes, int n_in,
                              void* d_out, int out_size)
{
    (void)in_sizes; (void)n_in; (void)out_size;

    const float* nf   = (const float*)d_in[0];
    const int*   ei   = (const int*)  d_in[1];
    const float* ef   = (const float*)d_in[2];
    const int*   bseg = (const int*)  d_in[3];
    const int*   pid  = (const int*)  d_in[4];
    const float* Wn   = (const float*)d_in[5];
    const float* bn   = (const float*)d_in[6];
    const float* We   = (const float*)d_in[7];
    const float* be   = (const float*)d_in[8];
    const float* Wm   = (const float*)d_in[9];
    const float* bm   = (const float*)d_in[10];
    const float* Wu   = (const float*)d_in[11];
    const float* bu   = (const float*)d_in[12];
    const float* lng  = (const float*)d_in[13];
    const float* lnb  = (const float*)d_in[14];
    const float* ctx  = (const float*)d_in[15];
    const float* gW1  = (const float*)d_in[16];
    const float* gb1  = (const float*)d_in[17];
    const float* glng = (const float*)d_in[18];
    const float* glnb = (const float*)d_in[19];
    const float* gW2  = (const float*)d_in[20];
    const float* gb2  = (const float*)d_in[21];
    const float* bW1  = (const float*)d_in[22];
    const float* bb1  = (const float*)d_in[23];
    const float* blng = (const float*)d_in[24];
    const float* blnb = (const float*)d_in[25];
    const float* bW2  = (const float*)d_in[26];
    const float* bb2  = (const float*)d_in[27];
    const float* pW1  = (const float*)d_in[28];
    const float* pb1  = (const float*)d_in[29];
    const float* pW2  = (const float*)d_in[30];
    const float* pb2  = (const float*)d_in[31];
    float* out = (float*)d_out;

    const int* src = ei;
    const int* dst = ei + EE;

    float *h_ptr, *agg_ptr, *t_ptr;
    __nv_bfloat16 *hhi, *hlo, *ehi, *elo;
    uint4 *wPkHi, *wPkLo;
    cudaGetSymbolAddress((void**)&h_ptr,   g_h);
    cudaGetSymbolAddress((void**)&agg_ptr, g_agg);
    cudaGetSymbolAddress((void**)&t_ptr,   g_t);
    cudaGetSymbolAddress((void**)&hhi,     g_hhi);
    cudaGetSymbolAddress((void**)&hlo,     g_hlo);
    cudaGetSymbolAddress((void**)&ehi,     g_ehi);
    cudaGetSymbolAddress((void**)&elo,     g_elo);
    cudaGetSymbolAddress((void**)&wPkHi,   g_wPkHi);
    cudaGetSymbolAddress((void**)&wPkLo,   g_wPkLo);

    cudaFuncSetAttribute(mma_gemm<1, 2>, cudaFuncAttributeMaxDynamicSharedMemorySize, MM_SMEM);
    cudaFuncSetAttribute(mma_gemm<1, 3>, cudaFuncAttributeMaxDynamicSharedMemorySize, MM_SMEM);
    cudaFuncSetAttribute(mma_gemm<0, 4>, cudaFuncAttributeMaxDynamicSharedMemorySize, MM_SMEM);

    dim3 thr(256);

    // pack weights into B-fragment order (hi/lo)
    pack_weights<<<384, 256>>>(Wm, Wu);

    // input embeddings: h (fp32 + bf16 split), e (bf16 split only)
    gemm_emb<1><<<dim3(2, NN / 128), thr>>>(nf, 69, 69, Wn, bn, h_ptr, hhi, hlo);
    gemm_emb<2><<<dim3(2, EE / 128), thr>>>(ef, 9, 9, We, be, nullptr, ehi, elo);

    // MPNN layers
    for (int l = 0; l < LLAY; l++) {
        const uint4* topHi = wPkHi + (size_t)l * 8192;
        const uint4* topLo = wPkLo + (size_t)l * 8192;
        const uint4* botHi = wPkHi + (size_t)(4 + l) * 8192;
        const uint4* botLo = wPkLo + (size_t)(4 + l) * 8192;
        const uint4* wuHi  = wPkHi + (size_t)(8 + l) * 8192;
        const uint4* wuLo  = wPkLo + (size_t)(8 + l) * 8192;

        cudaMemsetAsync(agg_ptr, 0, (size_t)NN * HIDD * sizeof(float), 0);

        // t = h @ Wm_top   (barrier-free warp-private mainloop)
        mma_gemm<1, 2><<<dim3(2, NN / 128), thr, MM_SMEM>>>(
            nullptr, hhi, hlo, topHi, topLo, nullptr, t_ptr, nullptr, nullptr, nullptr);

        // agg[dst] += relu(e @ Wm_bot + bm + t[src])
        mma_gemm<1, 3><<<dim3(2, EE / 128), thr, MM_SMEM>>>(
            nullptr, ehi, elo, botHi, botLo, bm + (size_t)l * 256, agg_ptr, src, dst, t_ptr);

        // h = h + relu(agg @ Wu + bu)   (fp32 convert path; residual fused, in place)
        mma_gemm<0, 4><<<dim3(2, NN / 128), thr, MM_SMEM>>>(
            agg_ptr, nullptr, nullptr, wuHi, wuLo, bu + (size_t)l * 256, h_ptr,
            nullptr, nullptr, h_ptr);

        // h = LN(h) in place + refresh bf16 split
        ln_kernel<<<NN / 8, 256>>>(lng + (size_t)l * 256, lnb + (size_t)l * 256);
    }

    // readout + FiLM + predictor
    seg_starts<<<NN / 256, 256>>>(bseg);
    readout_kernel<<<BBG, 256>>>();
    film_pred<<<BBG / 8, 256>>>(ctx, pid,
                                gW1, gb1, glng, glnb, gW2, gb2,
                                bW1, bb1, blng, blnb, bW2, bb2,
                                pW1, pb1, pW2, pb2, out);
}

// round 16
// speedup vs baseline: 1.1093x; 1.1093x over previous
#include <cuda_runtime.h>
#include <cuda_bf16.h>
#include <math.h>
#include <stdint.h>

#define NN   131072
#define EE   262144
#define BBG  4096
#define HIDD 256
#define LLAY 4

// ---------------- scratch (device globals; no allocation) ----------------
__device__ float g_h[(size_t)NN * HIDD];                 // fp32 node states
// pre-split activations in CHUNK-BLOCKED layout:
// block b=(row>>7)*8+(col>>5) holds 128 rows x 32 bf16 contiguous (4096 elems)
// elem idx = b*4096 + (row&127)*32 + (col&31)
__device__ __nv_bfloat16 g_hhi[(size_t)NN * HIDD];
__device__ __nv_bfloat16 g_hlo[(size_t)NN * HIDD];
__device__ __nv_bfloat16 g_ehi[(size_t)EE * HIDD];
__device__ __nv_bfloat16 g_elo[(size_t)EE * HIDD];
__device__ float g_agg[(size_t)NN * HIDD];
__device__ float g_t[(size_t)NN * HIDD];
__device__ float g_gout[(size_t)BBG * 512];
__device__ int   g_starts[BBG + 1];
// weights packed in mma.m16n8k16 B-fragment order
__device__ uint4 g_wPkHi[12 * 16 * 16 * 32];
__device__ uint4 g_wPkLo[12 * 16 * 16 * 32];

__device__ __forceinline__ size_t blk_idx(int row, int col) {
    return ((size_t)((row >> 7) * 8 + (col >> 5)) << 12)
         + (size_t)((row & 127) << 5) + (col & 31);
}

// ---------------- PTX helpers ----------------
__device__ __forceinline__ uint32_t smem_u32(const void* p) {
    uint32_t a;
    asm("{ .reg .u64 t; cvta.to.shared.u64 t, %1; cvt.u32.u64 %0, t; }" : "=r"(a) : "l"(p));
    return a;
}
#define LDSM4(r0, r1, r2, r3, addr) \
    asm volatile("ldmatrix.sync.aligned.m8n8.x4.shared.b16 {%0,%1,%2,%3}, [%4];" \
        : "=r"(r0), "=r"(r1), "=r"(r2), "=r"(r3) : "r"(addr))
#define MMA_BF16(c, a0, a1, a2, a3, b0, b1) \
    asm volatile("mma.sync.aligned.m16n8k16.row.col.f32.bf16.bf16.f32 " \
        "{%0,%1,%2,%3}, {%4,%5,%6,%7}, {%8,%9}, {%0,%1,%2,%3};" \
        : "+f"((c)[0]), "+f"((c)[1]), "+f"((c)[2]), "+f"((c)[3]) \
        : "r"(a0), "r"(a1), "r"(a2), "r"(a3), "r"(b0), "r"(b1))
#define CP_ASYNC16(dst, srcp) \
    asm volatile("cp.async.cg.shared.global [%0], [%1], 16;" :: "r"(dst), "l"(srcp) : "memory")
#define CP_COMMIT() asm volatile("cp.async.commit_group;" ::: "memory")
#define CP_WAIT0()  asm volatile("cp.async.wait_group 0;" ::: "memory")
#define CP_WAIT1()  asm volatile("cp.async.wait_group 1;" ::: "memory")

// ---------------- mma.sync bf16x3 GEMM: C[M,256] = A[M,256] @ WT^T ----------------
// 128x128 C tile/CTA, 8 warps 4(m)x2(n), warp tile 32x64, 2 CTA/SM.
// AMODE 1: A pre-split bf16 hi/lo, CHUNK-BLOCKED global layout -> fully coalesced
//          per-warp cp.async into warp-private smem. NO block barriers in mainloop.
// AMODE 0: A fp32 -> regs -> bf16 hi/lo -> block-shared smem (barrier per chunk).
// B: pre-packed fragment-order bf16 via LDG.128 (L1/L2-resident, hoisted).
// EPI 0: C=relu(acc+bias)   EPI 2: C=acc
// EPI 3: agg[dst] +=RED relu(acc+bias+Tg[src])
// EPI 4: C[r]=Tg[r]+relu(acc+bias)  (residual fuse; C may alias Tg)
#define WBUF    10240   // per-warp region (AMODE1): 2 bufs x (hi 2560 + lo 2560)
#define OFF_ALO0 10240  // AMODE0: lo offset within 20480B buffer
#define MM_SMEM 81920   // AMODE1: 8*10240; epilogue staging 128*132*4=67584 aliases

template <int AMODE, int EPI>
__global__ __launch_bounds__(256, 2)
void mma_gemm(const float* __restrict__ A,
              const __nv_bfloat16* __restrict__ Ahi,
              const __nv_bfloat16* __restrict__ Alo,
              const uint4* __restrict__ WhiPk,
              const uint4* __restrict__ WloPk,
              const float* __restrict__ bias, float* __restrict__ C,
              const int* __restrict__ src, const int* __restrict__ dst,
              const float* __restrict__ Tg)
{
    extern __shared__ char dsm[];
    const uint32_t sbase = smem_u32(dsm);

    const int tid  = threadIdx.x;
    const int wid  = tid >> 5;
    const int lane = tid & 31;
    const int row0 = blockIdx.y * 128;
    const int col0 = blockIdx.x * 128;

    const int wm = wid & 3;                 // warp row (32 rows)
    const int wn = wid >> 2;                // warp col (64 cols)
    const int nb0 = (col0 >> 4) + wn * 4;   // first 16-col block for this warp

    const int lrow  = tid >> 1;             // AMODE0 loader row 0..127
    const int lhalf = tid & 1;              // AMODE0 16-float half

    float c[2][8][4];
#pragma unroll
    for (int mt = 0; mt < 2; mt++)
#pragma unroll
        for (int nt = 0; nt < 8; nt++)
#pragma unroll
            for (int q = 0; q < 4; q++) c[mt][nt][q] = 0.f;

    const uint32_t frag_r = (uint32_t)(lane & 15);
    const uint32_t frag_c = (uint32_t)((lane >> 4) << 3);

    // ---- AMODE 1: per-warp coalesced async A loader (blocked layout) ----
    const uint32_t wbase = sbase + (uint32_t)wid * WBUF;
    auto lda_async = [&](int kc, int b) {
        uint32_t dbase = wbase + b * 5120;
        // warp band = 2KB hi + 2KB lo contiguous in blocked layout
        size_t eb = ((size_t)((row0 >> 7) * 8 + kc) << 12) + (size_t)(wm * 32) * 32;
        const char* sh = (const char*)(Ahi + eb);
        const char* sl = (const char*)(Alo + eb);
#pragma unroll
        for (int j = 0; j < 4; j++) {
            int p = j * 32 + lane;                       // 16B piece 0..127
            uint32_t dsmoff = dbase + (p >> 2) * 80 + (p & 3) * 16;
            CP_ASYNC16(dsmoff,        sh + (size_t)p * 16);
            CP_ASYNC16(dsmoff + 2560, sl + (size_t)p * 16);
        }
    };

    // ---- AMODE 0: block-shared convert loaders ----
    auto lda0 = [&](int kc, float4* va) {
        const float* ap = A + (size_t)(row0 + lrow) * 256 + kc * 32 + lhalf * 16;
        va[0] = *(const float4*)(ap + 0);
        va[1] = *(const float4*)(ap + 4);
        va[2] = *(const float4*)(ap + 8);
        va[3] = *(const float4*)(ap + 12);
    };
    auto sta0 = [&](int b, const float4* va) {
        float xs[16];
        xs[0] = va[0].x; xs[1] = va[0].y; xs[2]  = va[0].z; xs[3]  = va[0].w;
        xs[4] = va[1].x; xs[5] = va[1].y; xs[6]  = va[1].z; xs[7]  = va[1].w;
        xs[8] = va[2].x; xs[9] = va[2].y; xs[10] = va[2].z; xs[11] = va[2].w;
        xs[12] = va[3].x; xs[13] = va[3].y; xs[14] = va[3].z; xs[15] = va[3].w;
        union { __nv_bfloat16 bb[16]; uint4 u[2]; } Uh, Ul;
#pragma unroll
        for (int j = 0; j < 16; j++) {
            __nv_bfloat16 h = __float2bfloat16_rn(xs[j]);
            Uh.bb[j] = h;
            Ul.bb[j] = __float2bfloat16_rn(xs[j] - __bfloat162float(h));
        }
        char* arow = dsm + b * 20480 + lrow * 80 + lhalf * 32;
        *(uint4*)(arow)                 = Uh.u[0];
        *(uint4*)(arow + 16)            = Uh.u[1];
        *(uint4*)(arow + OFF_ALO0)      = Ul.u[0];
        *(uint4*)(arow + OFF_ALO0 + 16) = Ul.u[1];
    };

    auto compute = [&](int b, int kc) {
        const uint32_t boff    = (AMODE == 1) ? (wbase + b * 5120) : (sbase + b * 20480);
        const uint32_t loOff   = (AMODE == 1) ? 2560u : (uint32_t)OFF_ALO0;
        const uint32_t rowBase = (AMODE == 1) ? 0u : (uint32_t)(wm * 32);
#pragma unroll
        for (int ks = 0; ks < 2; ks++) {
            const int kb = kc * 2 + ks;
            uint4 BH[4], BL[4];
#pragma unroll
            for (int p = 0; p < 4; p++) {
                size_t bi = (size_t)((kb * 16 + nb0 + p) * 32 + lane);
                BH[p] = WhiPk[bi];
                BL[p] = WloPk[bi];
            }
            const uint32_t kkb = (uint32_t)(ks * 32) + frag_c * 2;
            uint32_t ah[2][4], al[2][4];
#pragma unroll
            for (int mt = 0; mt < 2; mt++) {
                uint32_t aaddr = boff + (rowBase + mt * 16 + frag_r) * 80 + kkb;
                LDSM4(ah[mt][0], ah[mt][1], ah[mt][2], ah[mt][3], aaddr);
                LDSM4(al[mt][0], al[mt][1], al[mt][2], al[mt][3], aaddr + loOff);
            }
#pragma unroll
            for (int p = 0; p < 4; p++) {
                MMA_BF16(c[0][2*p],   ah[0][0], ah[0][1], ah[0][2], ah[0][3], BH[p].x, BH[p].z);
                MMA_BF16(c[0][2*p+1], ah[0][0], ah[0][1], ah[0][2], ah[0][3], BH[p].y, BH[p].w);
                MMA_BF16(c[1][2*p],   ah[1][0], ah[1][1], ah[1][2], ah[1][3], BH[p].x, BH[p].z);
                MMA_BF16(c[1][2*p+1], ah[1][0], ah[1][1], ah[1][2], ah[1][3], BH[p].y, BH[p].w);

                MMA_BF16(c[0][2*p],   ah[0][0], ah[0][1], ah[0][2], ah[0][3], BL[p].x, BL[p].z);
                MMA_BF16(c[0][2*p+1], ah[0][0], ah[0][1], ah[0][2], ah[0][3], BL[p].y, BL[p].w);
                MMA_BF16(c[1][2*p],   ah[1][0], ah[1][1], ah[1][2], ah[1][3], BL[p].x, BL[p].z);
                MMA_BF16(c[1][2*p+1], ah[1][0], ah[1][1], ah[1][2], ah[1][3], BL[p].y, BL[p].w);

                MMA_BF16(c[0][2*p],   al[0][0], al[0][1], al[0][2], al[0][3], BH[p].x, BH[p].z);
                MMA_BF16(c[0][2*p+1], al[0][0], al[0][1], al[0][2], al[0][3], BH[p].y, BH[p].w);
                MMA_BF16(c[1][2*p],   al[1][0], al[1][1], al[1][2], al[1][3], BH[p].x, BH[p].z);
                MMA_BF16(c[1][2*p+1], al[1][0], al[1][1], al[1][2], al[1][3], BH[p].y, BH[p].w);
            }
        }
    };

    // ---- mainloop ----
    if (AMODE == 1) {
        lda_async(0, 0);
        CP_COMMIT();
        for (int kc = 0; kc < 8; kc++) {
            const int buf = kc & 1;
            if (kc < 7) {
                lda_async(kc + 1, buf ^ 1);
                CP_COMMIT();
                CP_WAIT1();
            } else {
                CP_WAIT0();
            }
            __syncwarp();
            compute(buf, kc);
        }
    } else {
        {
            float4 va0[4];
            lda0(0, va0);
            sta0(0, va0);
        }
        __syncthreads();
        for (int kc = 0; kc < 8; kc++) {
            const int buf = kc & 1;
            float4 va[4];
            if (kc < 7) lda0(kc + 1, va);
            compute(buf, kc);
            if (kc < 7) sta0(buf ^ 1, va);
            __syncthreads();
        }
    }

    // ---- stage C through smem ----
    __syncthreads();
    float* Csm = (float*)dsm;
    {
        int fr = lane >> 2;
        int fc = (lane & 3) * 2;
#pragma unroll
        for (int mt = 0; mt < 2; mt++) {
#pragma unroll
            for (int nt = 0; nt < 8; nt++) {
                int r = wm * 32 + mt * 16 + fr;
                int col = wn * 64 + nt * 8 + fc;
                *(float2*)&Csm[r * 132 + col]       = make_float2(c[mt][nt][0], c[mt][nt][1]);
                *(float2*)&Csm[(r + 8) * 132 + col] = make_float2(c[mt][nt][2], c[mt][nt][3]);
            }
        }
    }
    __syncthreads();

    // ---- final epilogue: thread handles row lrow, 64-col half ----
    {
        const int row  = lrow;
        const int coff = lhalf * 64;
        const float* crow = Csm + row * 132 + coff;
        const int grow = row0 + row;
        const int gc0  = col0 + coff;

        if (EPI == 2) {
            float* cp = C + (size_t)grow * 256 + gc0;
#pragma unroll
            for (int j = 0; j < 16; j++)
                *(float4*)(cp + 4 * j) = *(const float4*)(crow + 4 * j);
        } else if (EPI == 0) {
            float* cp = C + (size_t)grow * 256 + gc0;
            const float* bp = bias + gc0;
#pragma unroll
            for (int j = 0; j < 16; j++) {
                float4 v = *(const float4*)(crow + 4 * j);
                float4 bv = *(const float4*)(bp + 4 * j);
                float4 o;
                o.x = fmaxf(v.x + bv.x, 0.f);
                o.y = fmaxf(v.y + bv.y, 0.f);
                o.z = fmaxf(v.z + bv.z, 0.f);
                o.w = fmaxf(v.w + bv.w, 0.f);
                *(float4*)(cp + 4 * j) = o;
            }
        } else if (EPI == 4) {
            float* cp = C + (size_t)grow * 256 + gc0;
            const float* hp = Tg + (size_t)grow * 256 + gc0;
            const float* bp = bias + gc0;
#pragma unroll
            for (int j = 0; j < 16; j++) {
                float4 v = *(const float4*)(crow + 4 * j);
                float4 hv = *(const float4*)(hp + 4 * j);
                float4 bv = *(const float4*)(bp + 4 * j);
                float4 o;
                o.x = hv.x + fmaxf(v.x + bv.x, 0.f);
                o.y = hv.y + fmaxf(v.y + bv.y, 0.f);
                o.z = hv.z + fmaxf(v.z + bv.z, 0.f);
                o.w = hv.w + fmaxf(v.w + bv.w, 0.f);
                *(float4*)(cp + 4 * j) = o;
            }
        } else { // EPI == 3
            int sr = src[grow];
            int dn = dst[grow];
            const float* tp = Tg + (size_t)sr * 256 + gc0;
            const float* bp = bias + gc0;
            float* base = C + (size_t)dn * 256 + gc0;
#pragma unroll
            for (int j = 0; j < 16; j++) {
                float4 a = *(const float4*)(crow + 4 * j);
                float4 tv = *(const float4*)(tp + 4 * j);
                float4 bv = *(const float4*)(bp + 4 * j);
                float4 v;
                v.x = fmaxf(a.x + bv.x + tv.x, 0.f);
                v.y = fmaxf(a.y + bv.y + tv.y, 0.f);
                v.z = fmaxf(a.z + bv.z + tv.z, 0.f);
                v.w = fmaxf(a.w + bv.w + tv.w, 0.f);
                atomicAdd((float4*)(base + 4 * j), v);
            }
        }
    }
}

// ---------------- weight packing into B-fragment order (once per launch) ----------------
__global__ void pack_weights(const float* __restrict__ Wm, const float* __restrict__ Wu)
{
    int idx  = blockIdx.x * 256 + threadIdx.x;
    int lane = idx & 31;
    int nb   = (idx >> 5) & 15;
    int kb   = (idx >> 9) & 15;
    int m    = idx >> 13;

    const float* W = (m < 8)
        ? (Wm + (size_t)(m & 3) * 512 * 256 + (size_t)(m >> 2) * 256 * 256)
        : (Wu + (size_t)(m - 8) * 256 * 256);

    int k0 = kb * 16 + (lane & 3) * 2;
    int n0 = nb * 16 + (lane >> 2);

    union { __nv_bfloat16 b[2]; uint32_t u; } cvt;
    uint32_t ph[4], pl[4];
#pragma unroll
    for (int r = 0; r < 4; r++) {
        int kk = k0 + (r >> 1) * 8;
        int nn = n0 + (r & 1) * 8;
        float v0 = W[(size_t)kk * 256 + nn];
        float v1 = W[(size_t)(kk + 1) * 256 + nn];
        __nv_bfloat16 h0 = __float2bfloat16_rn(v0);
        __nv_bfloat16 h1 = __float2bfloat16_rn(v1);
        cvt.b[0] = h0; cvt.b[1] = h1;
        ph[r] = cvt.u;
        cvt.b[0] = __float2bfloat16_rn(v0 - __bfloat162float(h0));
        cvt.b[1] = __float2bfloat16_rn(v1 - __bfloat162float(h1));
        pl[r] = cvt.u;
    }
    g_wPkHi[idx] = make_uint4(ph[0], ph[1], ph[2], ph[3]);
    g_wPkLo[idx] = make_uint4(pl[0], pl[1], pl[2], pl[3]);
}

// ---------------- fp32 f32x2 SGEMM for ragged-K embeddings ----------------
// OUTM 1: write fp32 C AND blocked bf16 hi/lo (h)    OUTM 2: blocked bf16 hi/lo only (e)
#define DUP2(d, f)    asm("mov.b64 %0, {%1, %1};" : "=l"(d) : "f"(f))
#define FMA2(c, a, b) asm("fma.rn.f32x2 %0, %1, %2, %0;" : "+l"(c) : "l"(a), "l"(b))
#define UNPK2(lo, hi, v) asm("mov.b64 {%0, %1}, %2;" : "=f"(lo), "=f"(hi) : "l"(v))

template <int OUTM>
__global__ __launch_bounds__(256, 2)
void gemm_emb(const float* __restrict__ A, int lda, int K,
              const float* __restrict__ Bw,
              const float* __restrict__ bias,
              float* __restrict__ C,
              __nv_bfloat16* __restrict__ Chi,
              __nv_bfloat16* __restrict__ Clo)
{
    __shared__ float As[2][8][128];
    __shared__ float Bs[2][8][128];

    const int tid  = threadIdx.x;
    const int row0 = blockIdx.y * 128;
    const int col0 = blockIdx.x * 128;

    const int aRow = tid >> 1;
    const int aCol = (tid & 1) << 2;
    const int bRow = tid >> 5;
    const int bCol = (tid & 31) << 2;

    auto load_a = [&](int kt) -> float4 {
        float t0 = 0.f, t1 = 0.f, t2 = 0.f, t3 = 0.f;
        const float* arow = A + (size_t)(row0 + aRow) * lda;
        int k0 = kt + aCol;
        if (k0 + 0 < K) t0 = arow[k0 + 0];
        if (k0 + 1 < K) t1 = arow[k0 + 1];
        if (k0 + 2 < K) t2 = arow[k0 + 2];
        if (k0 + 3 < K) t3 = arow[k0 + 3];
        return make_float4(t0, t1, t2, t3);
    };
    auto load_b = [&](int kt) -> float4 {
        int kb = kt + bRow;
        if (kb >= K) return make_float4(0.f, 0.f, 0.f, 0.f);
        return *(const float4*)(Bw + (size_t)kb * 256 + col0 + bCol);
    };
    auto store_tile = [&](int p, float4 a4, float4 b4) {
        As[p][aCol + 0][aRow] = a4.x;
        As[p][aCol + 1][aRow] = a4.y;
        As[p][aCol + 2][aRow] = a4.z;
        As[p][aCol + 3][aRow] = a4.w;
        *(float4*)&Bs[p][bRow][bCol] = b4;
    };

    unsigned long long acc2[4][8];
#pragma unroll
    for (int i2 = 0; i2 < 4; i2++)
#pragma unroll
        for (int j = 0; j < 8; j++) acc2[i2][j] = 0ULL;

    const int tx = tid & 15;
    const int ty = tid >> 4;

    auto compute = [&](int p) {
#pragma unroll
        for (int kk = 0; kk < 8; kk++) {
            ulonglong2 aA = *(const ulonglong2*)&As[p][kk][ty * 4];
            ulonglong2 aB = *(const ulonglong2*)&As[p][kk][64 + ty * 4];
            unsigned long long a2[4] = {aA.x, aA.y, aB.x, aB.y};
            float4 b0 = *(const float4*)&Bs[p][kk][tx * 4];
            float4 b1 = *(const float4*)&Bs[p][kk][64 + tx * 4];
            unsigned long long bb2[8];
            DUP2(bb2[0], b0.x); DUP2(bb2[1], b0.y); DUP2(bb2[2], b0.z); DUP2(bb2[3], b0.w);
            DUP2(bb2[4], b1.x); DUP2(bb2[5], b1.y); DUP2(bb2[6], b1.z); DUP2(bb2[7], b1.w);
#pragma unroll
            for (int i2 = 0; i2 < 4; i2++)
#pragma unroll
                for (int j = 0; j < 8; j++)
                    FMA2(acc2[i2][j], a2[i2], bb2[j]);
        }
    };

    store_tile(0, load_a(0), load_b(0));
    __syncthreads();
    int p = 0;
    for (int kt = 8; kt < K; kt += 8) {
        float4 a4 = load_a(kt);
        float4 b4 = load_b(kt);
        compute(p);
        store_tile(p ^ 1, a4, b4);
        __syncthreads();
        p ^= 1;
    }
    compute(p);

    float acc[8][8];
#pragma unroll
    for (int i2 = 0; i2 < 4; i2++)
#pragma unroll
        for (int j = 0; j < 8; j++)
            UNPK2(acc[2 * i2][j], acc[2 * i2 + 1][j], acc2[i2][j]);

    float bb[8];
#pragma unroll
    for (int j = 0; j < 4; j++) {
        bb[j]     = bias[col0 + tx * 4 + j];
        bb[4 + j] = bias[col0 + 64 + tx * 4 + j];
    }
#pragma unroll
    for (int i = 0; i < 8; i++) {
        int lrow = (i < 4) ? (ty * 4 + i) : (64 + ty * 4 + (i - 4));
        int grow = row0 + lrow;
        int c1 = col0 + tx * 4;
        int c2 = col0 + 64 + tx * 4;
        float v[8];
#pragma unroll
        for (int j = 0; j < 8; j++) v[j] = fmaxf(acc[i][j] + bb[j], 0.f);

        if (OUTM == 1) {
            size_t base = (size_t)grow * 256 + col0;
            *(float4*)(C + base + tx * 4)      = make_float4(v[0], v[1], v[2], v[3]);
            *(float4*)(C + base + 64 + tx * 4) = make_float4(v[4], v[5], v[6], v[7]);
        }
        union { __nv_bfloat16 b[4]; uint2 u; } H0, H1, L0, L1;
#pragma unroll
        for (int j = 0; j < 4; j++) {
            __nv_bfloat16 h = __float2bfloat16_rn(v[j]);
            H0.b[j] = h;
            L0.b[j] = __float2bfloat16_rn(v[j] - __bfloat162float(h));
            __nv_bfloat16 h2 = __float2bfloat16_rn(v[4 + j]);
            H1.b[j] = h2;
            L1.b[j] = __float2bfloat16_rn(v[4 + j] - __bfloat162float(h2));
        }
        *(uint2*)(Chi + blk_idx(grow, c1)) = H0.u;
        *(uint2*)(Chi + blk_idx(grow, c2)) = H1.u;
        *(uint2*)(Clo + blk_idx(grow, c1)) = L0.u;
        *(uint2*)(Clo + blk_idx(grow, c2)) = L1.u;
    }
}

// ---------------- LayerNorm (in place) + blocked bf16 split ----------------
__global__ void ln_kernel(const float* __restrict__ lg,
                          const float* __restrict__ lb)
{
    int row  = blockIdx.x * 8 + (threadIdx.x >> 5);
    int lane = threadIdx.x & 31;
    float* hrow = g_h + (size_t)row * 256;

    float x[8];
    float4 h0 = *(const float4*)(hrow + lane * 4);
    float4 h1 = *(const float4*)(hrow + 128 + lane * 4);
    x[0] = h0.x; x[1] = h0.y; x[2] = h0.z; x[3] = h0.w;
    x[4] = h1.x; x[5] = h1.y; x[6] = h1.z; x[7] = h1.w;

    float s = 0.f, q = 0.f;
#pragma unroll
    for (int j = 0; j < 8; j++) { s += x[j]; q += x[j] * x[j]; }
#pragma unroll
    for (int o = 16; o > 0; o >>= 1) {
        s += __shfl_xor_sync(0xFFFFFFFFu, s, o);
        q += __shfl_xor_sync(0xFFFFFFFFu, q, o);
    }
    float mu  = s * (1.f / 256.f);
    float var = q * (1.f / 256.f) - mu * mu;
    float rs  = rsqrtf(var + 1e-5f);

    float4 g0 = *(const float4*)(lg + lane * 4);
    float4 g1 = *(const float4*)(lg + 128 + lane * 4);
    float4 b0 = *(const float4*)(lb + lane * 4);
    float4 b1 = *(const float4*)(lb + 128 + lane * 4);

    float y[8];
    y[0] = (x[0] - mu) * rs * g0.x + b0.x;
    y[1] = (x[1] - mu) * rs * g0.y + b0.y;
    y[2] = (x[2] - mu) * rs * g0.z + b0.z;
    y[3] = (x[3] - mu) * rs * g0.w + b0.w;
    y[4] = (x[4] - mu) * rs * g1.x + b1.x;
    y[5] = (x[5] - mu) * rs * g1.y + b1.y;
    y[6] = (x[6] - mu) * rs * g1.z + b1.z;
    y[7] = (x[7] - mu) * rs * g1.w + b1.w;
    *(float4*)(hrow + lane * 4)       = make_float4(y[0], y[1], y[2], y[3]);
    *(float4*)(hrow + 128 + lane * 4) = make_float4(y[4], y[5], y[6], y[7]);

    union { __nv_bfloat16 b[4]; uint2 u; } H0, H1, L0, L1;
#pragma unroll
    for (int j = 0; j < 4; j++) {
        __nv_bfloat16 h = __float2bfloat16_rn(y[j]);
        H0.b[j] = h;
        L0.b[j] = __float2bfloat16_rn(y[j] - __bfloat162float(h));
        __nv_bfloat16 h2 = __float2bfloat16_rn(y[4 + j]);
        H1.b[j] = h2;
        L1.b[j] = __float2bfloat16_rn(y[4 + j] - __bfloat162float(h2));
    }
    int c1 = lane * 4;
    int c2 = 128 + lane * 4;
    *(uint2*)(g_hhi + blk_idx(row, c1)) = H0.u;
    *(uint2*)(g_hhi + blk_idx(row, c2)) = H1.u;
    *(uint2*)(g_hlo + blk_idx(row, c1)) = L0.u;
    *(uint2*)(g_hlo + blk_idx(row, c2)) = L1.u;
}

// ---------------- segment starts from sorted b ----------------
__global__ void seg_starts(const int* __restrict__ b)
{
    int i = blockIdx.x * blockDim.x + threadIdx.x;
    if (i >= NN) return;
    int cur = b[i];
    if (i == 0) {
        for (int g = 0; g <= cur; g++) g_starts[g] = 0;
    } else {
        int prev = b[i - 1];
        if (prev != cur)
            for (int g = prev + 1; g <= cur; g++) g_starts[g] = i;
    }
    if (i == NN - 1)
        for (int g = cur + 1; g <= BBG; g++) g_starts[g] = NN;
}

// ---------------- readout: mean || max per graph ----------------
__global__ void readout_kernel(void)
{
    int g = blockIdx.x;
    int s = g_starts[g], en = g_starts[g + 1];
    int c = threadIdx.x;
    float sum = 0.f, mx = -INFINITY;
    for (int r = s; r < en; r++) {
        float v = g_h[(size_t)r * 256 + c];
        sum += v;
        mx = fmaxf(mx, v);
    }
    int   cnt   = en - s;
    float denom = (cnt > 0) ? (float)cnt : 1.f;
    g_gout[(size_t)g * 512 + c]       = sum / denom;
    g_gout[(size_t)g * 512 + 256 + c] = (cnt > 0) ? mx : 0.f;
}

// ---------------- FiLM + predictor, 8 graphs per block ----------------
__global__ __launch_bounds__(256)
void film_pred(const float* __restrict__ ctx, const int* __restrict__ pid,
               const float* __restrict__ gW1, const float* __restrict__ gb1,
               const float* __restrict__ glng, const float* __restrict__ glnb,
               const float* __restrict__ gW2, const float* __restrict__ gb2,
               const float* __restrict__ bW1, const float* __restrict__ bb1,
               const float* __restrict__ blng, const float* __restrict__ blnb,
               const float* __restrict__ bW2, const float* __restrict__ bb2,
               const float* __restrict__ pW1, const float* __restrict__ pb1,
               const float* __restrict__ pW2, const float* __restrict__ pb2,
               float* __restrict__ out)
{
    __shared__ float s_c[8][128];
    __shared__ float s_t[8][256];
    __shared__ float s_hmod[8][512];

    int tid = threadIdx.x;
    int g0  = blockIdx.x * 8;

    for (int i = tid; i < 8 * 128; i += 256) {
        int r = i >> 7, k = i & 127;
        s_c[r][k] = ctx[(size_t)pid[g0 + r] * 128 + k];
    }
    __syncthreads();

#pragma unroll
    for (int net = 0; net < 2; net++) {
        const float* W1 = net ? bW1 : gW1;
        const float* B1 = net ? bb1 : gb1;
        const float* LG = net ? blng : glng;
        const float* LB = net ? blnb : glnb;
        const float* W2 = net ? bW2 : gW2;
        const float* B2 = net ? bb2 : gb2;

        float a1[8];
#pragma unroll
        for (int r = 0; r < 8; r++) a1[r] = B1[tid];
        for (int k = 0; k < 128; k++) {
            float w = W1[k * 256 + tid];
#pragma unroll
            for (int r = 0; r < 8; r++) a1[r] += s_c[r][k] * w;
        }
#pragma unroll
        for (int r = 0; r < 8; r++) s_t[r][tid] = a1[r];
        __syncthreads();

        {
            int r = tid >> 5, lane = tid & 31;
            float x[8], s = 0.f, q = 0.f;
#pragma unroll
            for (int j = 0; j < 8; j++) {
                x[j] = s_t[r][lane + 32 * j];
                s += x[j]; q += x[j] * x[j];
            }
#pragma unroll
            for (int o = 16; o > 0; o >>= 1) {
                s += __shfl_xor_sync(0xFFFFFFFFu, s, o);
                q += __shfl_xor_sync(0xFFFFFFFFu, q, o);
            }
            float mu  = s * (1.f / 256.f);
            float var = q * (1.f / 256.f) - mu * mu;
            float rs  = rsqrtf(var + 1e-5f);
#pragma unroll
            for (int j = 0; j < 8; j++) {
                int cc = lane + 32 * j;
                float y = (x[j] - mu) * rs * LG[cc] + LB[cc];
                s_t[r][cc] = fmaxf(y, 0.f);
            }
        }
        __syncthreads();

        float a20[8], a21[8];
#pragma unroll
        for (int r = 0; r < 8; r++) { a20[r] = 0.f; a21[r] = 0.f; }
        for (int k = 0; k < 256; k++) {
            float w0 = W2[k * 512 + tid];
            float w1 = W2[k * 512 + tid + 256];
#pragma unroll
            for (int r = 0; r < 8; r++) {
                float t = s_t[r][k];
                a20[r] += t * w0;
                a21[r] += t * w1;
            }
        }
        float bc0 = B2[tid], bc1 = B2[tid + 256];
        if (net == 0) {
#pragma unroll
            for (int r = 0; r < 8; r++) {
                s_hmod[r][tid]       = (a20[r] + bc0) * g_gout[(size_t)(g0 + r) * 512 + tid];
                s_hmod[r][tid + 256] = (a21[r] + bc1) * g_gout[(size_t)(g0 + r) * 512 + tid + 256];
            }
        } else {
#pragma unroll
            for (int r = 0; r < 8; r++) {
                s_hmod[r][tid]       += a20[r] + bc0;
                s_hmod[r][tid + 256] += a21[r] + bc1;
            }
        }
        __syncthreads();
    }

    float az[8];
#pragma unroll
    for (int r = 0; r < 8; r++) az[r] = pb1[tid];
    for (int k = 0; k < 512; k++) {
        float w = pW1[k * 256 + tid];
#pragma unroll
        for (int r = 0; r < 8; r++) az[r] += s_hmod[r][k] * w;
    }
#pragma unroll
    for (int r = 0; r < 8; r++) s_t[r][tid] = fmaxf(az[r], 0.f);
    __syncthreads();

    {
        int r = tid >> 5, lane = tid & 31;
        float p = 0.f;
#pragma unroll
        for (int j = 0; j < 8; j++) {
            int cc = lane + 32 * j;
            p += s_t[r][cc] * pW2[cc];
        }
#pragma unroll
        for (int o = 16; o > 0; o >>= 1) p += __shfl_xor_sync(0xFFFFFFFFu, p, o);
        if (lane == 0) out[g0 + r] = p + pb2[0];
    }
}

// ---------------- host launcher ----------------
extern "C" void kernel_launch(void* const* d_in, const int* in_sizes, int n_in,
                              void* d_out, int out_size)
{
    (void)in_sizes; (void)n_in; (void)out_size;

    const float* nf   = (const float*)d_in[0];
    const int*   ei   = (const int*)  d_in[1];
    const float* ef   = (const float*)d_in[2];
    const int*   bseg = (const int*)  d_in[3];
    const int*   pid  = (const int*)  d_in[4];
    const float* Wn   = (const float*)d_in[5];
    const float* bn   = (const float*)d_in[6];
    const float* We   = (const float*)d_in[7];
    const float* be   = (const float*)d_in[8];
    const float* Wm   = (const float*)d_in[9];
    const float* bm   = (const float*)d_in[10];
    const float* Wu   = (const float*)d_in[11];
    const float* bu   = (const float*)d_in[12];
    const float* lng  = (const float*)d_in[13];
    const float* lnb  = (const float*)d_in[14];
    const float* ctx  = (const float*)d_in[15];
    const float* gW1  = (const float*)d_in[16];
    const float* gb1  = (const float*)d_in[17];
    const float* glng = (const float*)d_in[18];
    const float* glnb = (const float*)d_in[19];
    const float* gW2  = (const float*)d_in[20];
    const float* gb2  = (const float*)d_in[21];
    const float* bW1  = (const float*)d_in[22];
    const float* bb1  = (const float*)d_in[23];
    const float* blng = (const float*)d_in[24];
    const float* blnb = (const float*)d_in[25];
    const float* bW2  = (const float*)d_in[26];
    const float* bb2  = (const float*)d_in[27];
    const float* pW1  = (const float*)d_in[28];
    const float* pb1  = (const float*)d_in[29];
    const float* pW2  = (const float*)d_in[30];
    const float* pb2  = (const float*)d_in[31];
    float* out = (float*)d_out;

    const int* src = ei;
    const int* dst = ei + EE;

    float *h_ptr, *agg_ptr, *t_ptr;
    __nv_bfloat16 *hhi, *hlo, *ehi, *elo;
    uint4 *wPkHi, *wPkLo;
    cudaGetSymbolAddress((void**)&h_ptr,   g_h);
    cudaGetSymbolAddress((void**)&agg_ptr, g_agg);
    cudaGetSymbolAddress((void**)&t_ptr,   g_t);
    cudaGetSymbolAddress((void**)&hhi,     g_hhi);
    cudaGetSymbolAddress((void**)&hlo,     g_hlo);
    cudaGetSymbolAddress((void**)&ehi,     g_ehi);
    cudaGetSymbolAddress((void**)&elo,     g_elo);
    cudaGetSymbolAddress((void**)&wPkHi,   g_wPkHi);
    cudaGetSymbolAddress((void**)&wPkLo,   g_wPkLo);

    cudaFuncSetAttribute(mma_gemm<1, 2>, cudaFuncAttributeMaxDynamicSharedMemorySize, MM_SMEM);
    cudaFuncSetAttribute(mma_gemm<1, 3>, cudaFuncAttributeMaxDynamicSharedMemorySize, MM_SMEM);
    cudaFuncSetAttribute(mma_gemm<0, 4>, cudaFuncAttributeMaxDynamicSharedMemorySize, MM_SMEM);

    dim3 thr(256);

    // pack weights into B-fragment order (hi/lo)
    pack_weights<<<384, 256>>>(Wm, Wu);

    // input embeddings: h (fp32 + blocked bf16 split), e (blocked bf16 split only)
    gemm_emb<1><<<dim3(2, NN / 128), thr>>>(nf, 69, 69, Wn, bn, h_ptr, hhi, hlo);
    gemm_emb<2><<<dim3(2, EE / 128), thr>>>(ef, 9, 9, We, be, nullptr, ehi, elo);

    // MPNN layers
    for (int l = 0; l < LLAY; l++) {
        const uint4* topHi = wPkHi + (size_t)l * 8192;
        const uint4* topLo = wPkLo + (size_t)l * 8192;
        const uint4* botHi = wPkHi + (size_t)(4 + l) * 8192;
        const uint4* botLo = wPkLo + (size_t)(4 + l) * 8192;
        const uint4* wuHi  = wPkHi + (size_t)(8 + l) * 8192;
        const uint4* wuLo  = wPkLo + (size_t)(8 + l) * 8192;

        cudaMemsetAsync(agg_ptr, 0, (size_t)NN * HIDD * sizeof(float), 0);

        // t = h @ Wm_top   (barrier-free, coalesced blocked A)
        mma_gemm<1, 2><<<dim3(2, NN / 128), thr, MM_SMEM>>>(
            nullptr, hhi, hlo, topHi, topLo, nullptr, t_ptr, nullptr, nullptr, nullptr);

        // agg[dst] += relu(e @ Wm_bot + bm + t[src])
        mma_gemm<1, 3><<<dim3(2, EE / 128), thr, MM_SMEM>>>(
            nullptr, ehi, elo, botHi, botLo, bm + (size_t)l * 256, agg_ptr, src, dst, t_ptr);

        // h = h + relu(agg @ Wu + bu)   (fp32 convert path; residual fused, in place)
        mma_gemm<0, 4><<<dim3(2, NN / 128), thr, MM_SMEM>>>(
            agg_ptr, nullptr, nullptr, wuHi, wuLo, bu + (size_t)l * 256, h_ptr,
            nullptr, nullptr, h_ptr);

        // h = LN(h) in place + refresh blocked bf16 split
        ln_kernel<<<NN / 8, 256>>>(lng + (size_t)l * 256, lnb + (size_t)l * 256);
    }

    // readout + FiLM + predictor
    seg_starts<<<NN / 256, 256>>>(bseg);
    readout_kernel<<<BBG, 256>>>();
    film_pred<<<BBG / 8, 256>>>(ctx, pid,
                                gW1, gb1, glng, glnb, gW2, gb2,
                                bW1, bb1, blng, blnb, bW2, bb2,
                                pW1, pb1, pW2, pb2, out);
}

// round 17
// speedup vs baseline: 1.1322x; 1.0207x over previous
#include <cuda_runtime.h>
#include <cuda_bf16.h>
#include <math.h>
#include <stdint.h>

#define NN   131072
#define EE   262144
#define BBG  4096
#define HIDD 256
#define LLAY 4

// ---------------- scratch (device globals; no allocation) ----------------
__device__ float g_h[(size_t)NN * HIDD];                 // fp32 node states
// pre-split activations, CHUNK-BLOCKED + ks-major layout:
// idx = ((row>>7)*8 + (col>>5))*4096 + ((col>>4)&1)*2048 + (row&127)*16 + (col&15)
__device__ __nv_bfloat16 g_hhi[(size_t)NN * HIDD];
__device__ __nv_bfloat16 g_hlo[(size_t)NN * HIDD];
__device__ __nv_bfloat16 g_ehi[(size_t)EE * HIDD];
__device__ __nv_bfloat16 g_elo[(size_t)EE * HIDD];
__device__ float g_agg[(size_t)NN * HIDD];
__device__ float g_t[(size_t)NN * HIDD];
__device__ float g_gout[(size_t)BBG * 512];
__device__ int   g_starts[BBG + 1];
// weights packed in mma.m16n8k16 B-fragment order
__device__ uint4 g_wPkHi[12 * 16 * 16 * 32];
__device__ uint4 g_wPkLo[12 * 16 * 16 * 32];

__device__ __forceinline__ size_t blk_idx(int row, int col) {
    return ((size_t)((row >> 7) * 8 + (col >> 5)) << 12)
         + ((size_t)((col >> 4) & 1) << 11)
         + (size_t)((row & 127) << 4) + (col & 15);
}

// ---------------- PTX helpers ----------------
__device__ __forceinline__ uint32_t smem_u32(const void* p) {
    uint32_t a;
    asm("{ .reg .u64 t; cvta.to.shared.u64 t, %1; cvt.u32.u64 %0, t; }" : "=r"(a) : "l"(p));
    return a;
}
#define LDSM4(r0, r1, r2, r3, addr) \
    asm volatile("ldmatrix.sync.aligned.m8n8.x4.shared.b16 {%0,%1,%2,%3}, [%4];" \
        : "=r"(r0), "=r"(r1), "=r"(r2), "=r"(r3) : "r"(addr))
#define MMA_BF16(c, a0, a1, a2, a3, b0, b1) \
    asm volatile("mma.sync.aligned.m16n8k16.row.col.f32.bf16.bf16.f32 " \
        "{%0,%1,%2,%3}, {%4,%5,%6,%7}, {%8,%9}, {%0,%1,%2,%3};" \
        : "+f"((c)[0]), "+f"((c)[1]), "+f"((c)[2]), "+f"((c)[3]) \
        : "r"(a0), "r"(a1), "r"(a2), "r"(a3), "r"(b0), "r"(b1))
#define CP_ASYNC16(dst, srcp) \
    asm volatile("cp.async.cg.shared.global [%0], [%1], 16;" :: "r"(dst), "l"(srcp) : "memory")
#define CP_COMMIT() asm volatile("cp.async.commit_group;" ::: "memory")
#define CP_WAIT0()  asm volatile("cp.async.wait_group 0;" ::: "memory")
#define CP_WAIT1()  asm volatile("cp.async.wait_group 1;" ::: "memory")

// ---------------- mma.sync bf16x3 GEMM: C[M,256] = A[M,256] @ WT^T ----------------
// 128x128 C tile/CTA, 8 warps 4(m)x2(n), warp tile 32x64, 2 CTA/SM.
// AMODE 1: pre-split bf16 A, blocked layout -> per-warp cp.async, ks-granular
//          double buffer (48KB smem/CTA -> B weights become L1-resident).
//          Fully barrier-free.
// AMODE 0: A fp32 -> regs -> bf16 hi/lo -> block smem (barrier per chunk).
// B: pre-packed fragment-order bf16 via LDG.128 (L1-resident).
// Epilogues write DIRECTLY from fragments (no smem staging):
// EPI 0: relu(acc+bias)  EPI 2: acc  EPI 3: agg[dst]+=RED relu(acc+bias+Tg[src])
// EPI 4: C=Tg+relu(acc+bias) (residual; C aliases Tg)
#define KSBUF    3072      // per ks buffer: hi 1536 (32row x 48B) + lo 1536
#define WREG     6144      // per warp: 2 ks buffers
#define SM1      49152     // AMODE1 smem: 8 warps * 6144
#define OFF_ALO0 10240
#define SM0      40960     // AMODE0 smem: 2 x 20480

template <int AMODE, int EPI>
__global__ __launch_bounds__(256, 2)
void mma_gemm(const float* __restrict__ A,
              const __nv_bfloat16* __restrict__ Ahi,
              const __nv_bfloat16* __restrict__ Alo,
              const uint4* __restrict__ WhiPk,
              const uint4* __restrict__ WloPk,
              const float* __restrict__ bias, float* __restrict__ C,
              const int* __restrict__ src, const int* __restrict__ dst,
              const float* __restrict__ Tg)
{
    extern __shared__ char dsm[];
    const uint32_t sbase = smem_u32(dsm);

    const int tid  = threadIdx.x;
    const int wid  = tid >> 5;
    const int lane = tid & 31;
    const int row0 = blockIdx.y * 128;
    const int col0 = blockIdx.x * 128;

    const int wm = wid & 3;
    const int wn = wid >> 2;
    const int nb0 = (col0 >> 4) + wn * 4;

    const int lrow  = tid >> 1;   // AMODE0 loader row
    const int lhalf = tid & 1;

    float c[2][8][4];
#pragma unroll
    for (int mt = 0; mt < 2; mt++)
#pragma unroll
        for (int nt = 0; nt < 8; nt++)
#pragma unroll
            for (int q = 0; q < 4; q++) c[mt][nt][q] = 0.f;

    const uint32_t frag_r = (uint32_t)(lane & 15);
    const uint32_t frag_c = (uint32_t)((lane >> 4) << 3);

    const uint32_t wbase = sbase + (uint32_t)wid * WREG;

    // ---- AMODE1: per-warp ks-granularity async loader (coalesced, blocked) ----
    auto lda_ks = [&](int ksc, int b) {
        uint32_t d = wbase + b * KSBUF + lane * 48;
        size_t eb = ((size_t)((row0 >> 7) * 8 + (ksc >> 1)) << 12)
                  + ((size_t)(ksc & 1) << 11) + (size_t)(wm * 32) * 16;
        const char* sh = (const char*)(Ahi + eb) + (size_t)lane * 32;
        const char* sl = (const char*)(Alo + eb) + (size_t)lane * 32;
        CP_ASYNC16(d,          sh);
        CP_ASYNC16(d + 16,     sh + 16);
        CP_ASYNC16(d + 1536,      sl);
        CP_ASYNC16(d + 1536 + 16, sl + 16);
    };

    // ---- AMODE0 loaders (fp32 convert, block smem) ----
    auto lda0 = [&](int kc, float4* va) {
        const float* ap = A + (size_t)(row0 + lrow) * 256 + kc * 32 + lhalf * 16;
        va[0] = *(const float4*)(ap + 0);
        va[1] = *(const float4*)(ap + 4);
        va[2] = *(const float4*)(ap + 8);
        va[3] = *(const float4*)(ap + 12);
    };
    auto sta0 = [&](int b, const float4* va) {
        float xs[16];
        xs[0] = va[0].x; xs[1] = va[0].y; xs[2]  = va[0].z; xs[3]  = va[0].w;
        xs[4] = va[1].x; xs[5] = va[1].y; xs[6]  = va[1].z; xs[7]  = va[1].w;
        xs[8] = va[2].x; xs[9] = va[2].y; xs[10] = va[2].z; xs[11] = va[2].w;
        xs[12] = va[3].x; xs[13] = va[3].y; xs[14] = va[3].z; xs[15] = va[3].w;
        union { __nv_bfloat16 bb[16]; uint4 u[2]; } Uh, Ul;
#pragma unroll
        for (int j = 0; j < 16; j++) {
            __nv_bfloat16 h = __float2bfloat16_rn(xs[j]);
            Uh.bb[j] = h;
            Ul.bb[j] = __float2bfloat16_rn(xs[j] - __bfloat162float(h));
        }
        char* arow = dsm + b * 20480 + lrow * 80 + lhalf * 32;
        *(uint4*)(arow)                 = Uh.u[0];
        *(uint4*)(arow + 16)            = Uh.u[1];
        *(uint4*)(arow + OFF_ALO0)      = Ul.u[0];
        *(uint4*)(arow + OFF_ALO0 + 16) = Ul.u[1];
    };

    // ---- one ks step: ahibase points at hi data for this warp's rows ----
    auto compute_ks = [&](uint32_t ahibase, uint32_t stride, uint32_t loOff, int kb) {
        uint4 BH[4], BL[4];
#pragma unroll
        for (int p = 0; p < 4; p++) {
            size_t bi = (size_t)((kb * 16 + nb0 + p) * 32 + lane);
            BH[p] = WhiPk[bi];
            BL[p] = WloPk[bi];
        }
        uint32_t ah[2][4], al[2][4];
#pragma unroll
        for (int mt = 0; mt < 2; mt++) {
            uint32_t aaddr = ahibase + (mt * 16 + frag_r) * stride + frag_c * 2;
            LDSM4(ah[mt][0], ah[mt][1], ah[mt][2], ah[mt][3], aaddr);
            LDSM4(al[mt][0], al[mt][1], al[mt][2], al[mt][3], aaddr + loOff);
        }
#pragma unroll
        for (int p = 0; p < 4; p++) {
            MMA_BF16(c[0][2*p],   ah[0][0], ah[0][1], ah[0][2], ah[0][3], BH[p].x, BH[p].z);
            MMA_BF16(c[0][2*p+1], ah[0][0], ah[0][1], ah[0][2], ah[0][3], BH[p].y, BH[p].w);
            MMA_BF16(c[1][2*p],   ah[1][0], ah[1][1], ah[1][2], ah[1][3], BH[p].x, BH[p].z);
            MMA_BF16(c[1][2*p+1], ah[1][0], ah[1][1], ah[1][2], ah[1][3], BH[p].y, BH[p].w);

            MMA_BF16(c[0][2*p],   ah[0][0], ah[0][1], ah[0][2], ah[0][3], BL[p].x, BL[p].z);
            MMA_BF16(c[0][2*p+1], ah[0][0], ah[0][1], ah[0][2], ah[0][3], BL[p].y, BL[p].w);
            MMA_BF16(c[1][2*p],   ah[1][0], ah[1][1], ah[1][2], ah[1][3], BL[p].x, BL[p].z);
            MMA_BF16(c[1][2*p+1], ah[1][0], ah[1][1], ah[1][2], ah[1][3], BL[p].y, BL[p].w);

            MMA_BF16(c[0][2*p],   al[0][0], al[0][1], al[0][2], al[0][3], BH[p].x, BH[p].z);
            MMA_BF16(c[0][2*p+1], al[0][0], al[0][1], al[0][2], al[0][3], BH[p].y, BH[p].w);
            MMA_BF16(c[1][2*p],   al[1][0], al[1][1], al[1][2], al[1][3], BH[p].x, BH[p].z);
            MMA_BF16(c[1][2*p+1], al[1][0], al[1][1], al[1][2], al[1][3], BH[p].y, BH[p].w);
        }
    };

    // ---- mainloop ----
    if (AMODE == 1) {
        lda_ks(0, 0);
        CP_COMMIT();
        for (int ksc = 0; ksc < 16; ksc++) {
            const int buf = ksc & 1;
            if (ksc < 15) {
                lda_ks(ksc + 1, buf ^ 1);
                CP_COMMIT();
                CP_WAIT1();
            } else {
                CP_WAIT0();
            }
            __syncwarp();
            compute_ks(wbase + buf * KSBUF, 48u, 1536u, ksc);
        }
    } else {
        {
            float4 va0[4];
            lda0(0, va0);
            sta0(0, va0);
        }
        __syncthreads();
        for (int kc = 0; kc < 8; kc++) {
            const int buf = kc & 1;
            float4 va[4];
            if (kc < 7) lda0(kc + 1, va);
            uint32_t abase = sbase + buf * 20480 + (uint32_t)(wm * 32) * 80;
            compute_ks(abase,      80u, (uint32_t)OFF_ALO0, kc * 2 + 0);
            compute_ks(abase + 32, 80u, (uint32_t)OFF_ALO0, kc * 2 + 1);
            if (kc < 7) sta0(buf ^ 1, va);
            __syncthreads();
        }
    }

    // ---- direct epilogue from fragments (no smem staging, no barriers) ----
    {
        const int fr = lane >> 2;
        const int fc = (lane & 3) * 2;
#pragma unroll
        for (int mt = 0; mt < 2; mt++) {
            const int r0g = row0 + wm * 32 + mt * 16 + fr;
            const int r1g = r0g + 8;
            int sr0 = 0, dn0 = 0, sr1 = 0, dn1 = 0;
            if (EPI == 3) {
                sr0 = src[r0g]; dn0 = dst[r0g];
                sr1 = src[r1g]; dn1 = dst[r1g];
            }
#pragma unroll
            for (int nt = 0; nt < 8; nt++) {
                const int gc = col0 + wn * 64 + nt * 8 + fc;
                float2 v0 = make_float2(c[mt][nt][0], c[mt][nt][1]);
                float2 v1 = make_float2(c[mt][nt][2], c[mt][nt][3]);

                if (EPI == 2) {
                    *(float2*)(C + (size_t)r0g * 256 + gc) = v0;
                    *(float2*)(C + (size_t)r1g * 256 + gc) = v1;
                } else if (EPI == 0) {
                    float2 bv = __ldg((const float2*)(bias + gc));
                    v0.x = fmaxf(v0.x + bv.x, 0.f); v0.y = fmaxf(v0.y + bv.y, 0.f);
                    v1.x = fmaxf(v1.x + bv.x, 0.f); v1.y = fmaxf(v1.y + bv.y, 0.f);
                    *(float2*)(C + (size_t)r0g * 256 + gc) = v0;
                    *(float2*)(C + (size_t)r1g * 256 + gc) = v1;
                } else if (EPI == 4) {
                    float2 bv = __ldg((const float2*)(bias + gc));
                    float2 h0 = __ldcg((const float2*)(Tg + (size_t)r0g * 256 + gc));
                    float2 h1 = __ldcg((const float2*)(Tg + (size_t)r1g * 256 + gc));
                    float2 o0, o1;
                    o0.x = h0.x + fmaxf(v0.x + bv.x, 0.f);
                    o0.y = h0.y + fmaxf(v0.y + bv.y, 0.f);
                    o1.x = h1.x + fmaxf(v1.x + bv.x, 0.f);
                    o1.y = h1.y + fmaxf(v1.y + bv.y, 0.f);
                    *(float2*)(C + (size_t)r0g * 256 + gc) = o0;
                    *(float2*)(C + (size_t)r1g * 256 + gc) = o1;
                } else { // EPI == 3
                    float2 bv = __ldg((const float2*)(bias + gc));
                    float2 t0 = __ldcg((const float2*)(Tg + (size_t)sr0 * 256 + gc));
                    float2 t1 = __ldcg((const float2*)(Tg + (size_t)sr1 * 256 + gc));
                    float2 o0, o1;
                    o0.x = fmaxf(v0.x + bv.x + t0.x, 0.f);
                    o0.y = fmaxf(v0.y + bv.y + t0.y, 0.f);
                    o1.x = fmaxf(v1.x + bv.x + t1.x, 0.f);
                    o1.y = fmaxf(v1.y + bv.y + t1.y, 0.f);
                    atomicAdd((float2*)(C + (size_t)dn0 * 256 + gc), o0);
                    atomicAdd((float2*)(C + (size_t)dn1 * 256 + gc), o1);
                }
            }
        }
    }
}

// ---------------- weight packing into B-fragment order (once per launch) ----------------
__global__ void pack_weights(const float* __restrict__ Wm, const float* __restrict__ Wu)
{
    int idx  = blockIdx.x * 256 + threadIdx.x;
    int lane = idx & 31;
    int nb   = (idx >> 5) & 15;
    int kb   = (idx >> 9) & 15;
    int m    = idx >> 13;

    const float* W = (m < 8)
        ? (Wm + (size_t)(m & 3) * 512 * 256 + (size_t)(m >> 2) * 256 * 256)
        : (Wu + (size_t)(m - 8) * 256 * 256);

    int k0 = kb * 16 + (lane & 3) * 2;
    int n0 = nb * 16 + (lane >> 2);

    union { __nv_bfloat16 b[2]; uint32_t u; } cvt;
    uint32_t ph[4], pl[4];
#pragma unroll
    for (int r = 0; r < 4; r++) {
        int kk = k0 + (r >> 1) * 8;
        int nn = n0 + (r & 1) * 8;
        float v0 = W[(size_t)kk * 256 + nn];
        float v1 = W[(size_t)(kk + 1) * 256 + nn];
        __nv_bfloat16 h0 = __float2bfloat16_rn(v0);
        __nv_bfloat16 h1 = __float2bfloat16_rn(v1);
        cvt.b[0] = h0; cvt.b[1] = h1;
        ph[r] = cvt.u;
        cvt.b[0] = __float2bfloat16_rn(v0 - __bfloat162float(h0));
        cvt.b[1] = __float2bfloat16_rn(v1 - __bfloat162float(h1));
        pl[r] = cvt.u;
    }
    g_wPkHi[idx] = make_uint4(ph[0], ph[1], ph[2], ph[3]);
    g_wPkLo[idx] = make_uint4(pl[0], pl[1], pl[2], pl[3]);
}

// ---------------- fp32 f32x2 SGEMM for ragged-K embeddings ----------------
// OUTM 1: fp32 C AND blocked bf16 hi/lo (h)    OUTM 2: blocked bf16 hi/lo only (e)
#define DUP2(d, f)    asm("mov.b64 %0, {%1, %1};" : "=l"(d) : "f"(f))
#define FMA2(c, a, b) asm("fma.rn.f32x2 %0, %1, %2, %0;" : "+l"(c) : "l"(a), "l"(b))
#define UNPK2(lo, hi, v) asm("mov.b64 {%0, %1}, %2;" : "=f"(lo), "=f"(hi) : "l"(v))

template <int OUTM>
__global__ __launch_bounds__(256, 2)
void gemm_emb(const float* __restrict__ A, int lda, int K,
              const float* __restrict__ Bw,
              const float* __restrict__ bias,
              float* __restrict__ C,
              __nv_bfloat16* __restrict__ Chi,
              __nv_bfloat16* __restrict__ Clo)
{
    __shared__ float As[2][8][128];
    __shared__ float Bs[2][8][128];

    const int tid  = threadIdx.x;
    const int row0 = blockIdx.y * 128;
    const int col0 = blockIdx.x * 128;

    const int aRow = tid >> 1;
    const int aCol = (tid & 1) << 2;
    const int bRow = tid >> 5;
    const int bCol = (tid & 31) << 2;

    auto load_a = [&](int kt) -> float4 {
        float t0 = 0.f, t1 = 0.f, t2 = 0.f, t3 = 0.f;
        const float* arow = A + (size_t)(row0 + aRow) * lda;
        int k0 = kt + aCol;
        if (k0 + 0 < K) t0 = arow[k0 + 0];
        if (k0 + 1 < K) t1 = arow[k0 + 1];
        if (k0 + 2 < K) t2 = arow[k0 + 2];
        if (k0 + 3 < K) t3 = arow[k0 + 3];
        return make_float4(t0, t1, t2, t3);
    };
    auto load_b = [&](int kt) -> float4 {
        int kb = kt + bRow;
        if (kb >= K) return make_float4(0.f, 0.f, 0.f, 0.f);
        return *(const float4*)(Bw + (size_t)kb * 256 + col0 + bCol);
    };
    auto store_tile = [&](int p, float4 a4, float4 b4) {
        As[p][aCol + 0][aRow] = a4.x;
        As[p][aCol + 1][aRow] = a4.y;
        As[p][aCol + 2][aRow] = a4.z;
        As[p][aCol + 3][aRow] = a4.w;
        *(float4*)&Bs[p][bRow][bCol] = b4;
    };

    unsigned long long acc2[4][8];
#pragma unroll
    for (int i2 = 0; i2 < 4; i2++)
#pragma unroll
        for (int j = 0; j < 8; j++) acc2[i2][j] = 0ULL;

    const int tx = tid & 15;
    const int ty = tid >> 4;

    auto compute = [&](int p) {
#pragma unroll
        for (int kk = 0; kk < 8; kk++) {
            ulonglong2 aA = *(const ulonglong2*)&As[p][kk][ty * 4];
            ulonglong2 aB = *(const ulonglong2*)&As[p][kk][64 + ty * 4];
            unsigned long long a2[4] = {aA.x, aA.y, aB.x, aB.y};
            float4 b0 = *(const float4*)&Bs[p][kk][tx * 4];
            float4 b1 = *(const float4*)&Bs[p][kk][64 + tx * 4];
            unsigned long long bb2[8];
            DUP2(bb2[0], b0.x); DUP2(bb2[1], b0.y); DUP2(bb2[2], b0.z); DUP2(bb2[3], b0.w);
            DUP2(bb2[4], b1.x); DUP2(bb2[5], b1.y); DUP2(bb2[6], b1.z); DUP2(bb2[7], b1.w);
#pragma unroll
            for (int i2 = 0; i2 < 4; i2++)
#pragma unroll
                for (int j = 0; j < 8; j++)
                    FMA2(acc2[i2][j], a2[i2], bb2[j]);
        }
    };

    store_tile(0, load_a(0), load_b(0));
    __syncthreads();
    int p = 0;
    for (int kt = 8; kt < K; kt += 8) {
        float4 a4 = load_a(kt);
        float4 b4 = load_b(kt);
        compute(p);
        store_tile(p ^ 1, a4, b4);
        __syncthreads();
        p ^= 1;
    }
    compute(p);

    float acc[8][8];
#pragma unroll
    for (int i2 = 0; i2 < 4; i2++)
#pragma unroll
        for (int j = 0; j < 8; j++)
            UNPK2(acc[2 * i2][j], acc[2 * i2 + 1][j], acc2[i2][j]);

    float bb[8];
#pragma unroll
    for (int j = 0; j < 4; j++) {
        bb[j]     = bias[col0 + tx * 4 + j];
        bb[4 + j] = bias[col0 + 64 + tx * 4 + j];
    }
#pragma unroll
    for (int i = 0; i < 8; i++) {
        int lrow = (i < 4) ? (ty * 4 + i) : (64 + ty * 4 + (i - 4));
        int grow = row0 + lrow;
        int c1 = col0 + tx * 4;
        int c2 = col0 + 64 + tx * 4;
        float v[8];
#pragma unroll
        for (int j = 0; j < 8; j++) v[j] = fmaxf(acc[i][j] + bb[j], 0.f);

        if (OUTM == 1) {
            size_t base = (size_t)grow * 256 + col0;
            *(float4*)(C + base + tx * 4)      = make_float4(v[0], v[1], v[2], v[3]);
            *(float4*)(C + base + 64 + tx * 4) = make_float4(v[4], v[5], v[6], v[7]);
        }
        union { __nv_bfloat16 b[4]; uint2 u; } H0, H1, L0, L1;
#pragma unroll
        for (int j = 0; j < 4; j++) {
            __nv_bfloat16 h = __float2bfloat16_rn(v[j]);
            H0.b[j] = h;
            L0.b[j] = __float2bfloat16_rn(v[j] - __bfloat162float(h));
            __nv_bfloat16 h2 = __float2bfloat16_rn(v[4 + j]);
            H1.b[j] = h2;
            L1.b[j] = __float2bfloat16_rn(v[4 + j] - __bfloat162float(h2));
        }
        *(uint2*)(Chi + blk_idx(grow, c1)) = H0.u;
        *(uint2*)(Chi + blk_idx(grow, c2)) = H1.u;
        *(uint2*)(Clo + blk_idx(grow, c1)) = L0.u;
        *(uint2*)(Clo + blk_idx(grow, c2)) = L1.u;
    }
}

// ---------------- LayerNorm (in place) + blocked bf16 split ----------------
__global__ void ln_kernel(const float* __restrict__ lg,
                          const float* __restrict__ lb)
{
    int row  = blockIdx.x * 8 + (threadIdx.x >> 5);
    int lane = threadIdx.x & 31;
    float* hrow = g_h + (size_t)row * 256;

    float x[8];
    float4 h0 = *(const float4*)(hrow + lane * 4);
    float4 h1 = *(const float4*)(hrow + 128 + lane * 4);
    x[0] = h0.x; x[1] = h0.y; x[2] = h0.z; x[3] = h0.w;
    x[4] = h1.x; x[5] = h1.y; x[6] = h1.z; x[7] = h1.w;

    float s = 0.f, q = 0.f;
#pragma unroll
    for (int j = 0; j < 8; j++) { s += x[j]; q += x[j] * x[j]; }
#pragma unroll
    for (int o = 16; o > 0; o >>= 1) {
        s += __shfl_xor_sync(0xFFFFFFFFu, s, o);
        q += __shfl_xor_sync(0xFFFFFFFFu, q, o);
    }
    float mu  = s * (1.f / 256.f);
    float var = q * (1.f / 256.f) - mu * mu;
    float rs  = rsqrtf(var + 1e-5f);

    float4 g0 = *(const float4*)(lg + lane * 4);
    float4 g1 = *(const float4*)(lg + 128 + lane * 4);
    float4 b0 = *(const float4*)(lb + lane * 4);
    float4 b1 = *(const float4*)(lb + 128 + lane * 4);

    float y[8];
    y[0] = (x[0] - mu) * rs * g0.x + b0.x;
    y[1] = (x[1] - mu) * rs * g0.y + b0.y;
    y[2] = (x[2] - mu) * rs * g0.z + b0.z;
    y[3] = (x[3] - mu) * rs * g0.w + b0.w;
    y[4] = (x[4] - mu) * rs * g1.x + b1.x;
    y[5] = (x[5] - mu) * rs * g1.y + b1.y;
    y[6] = (x[6] - mu) * rs * g1.z + b1.z;
    y[7] = (x[7] - mu) * rs * g1.w + b1.w;
    *(float4*)(hrow + lane * 4)       = make_float4(y[0], y[1], y[2], y[3]);
    *(float4*)(hrow + 128 + lane * 4) = make_float4(y[4], y[5], y[6], y[7]);

    union { __nv_bfloat16 b[4]; uint2 u; } H0, H1, L0, L1;
#pragma unroll
    for (int j = 0; j < 4; j++) {
        __nv_bfloat16 h = __float2bfloat16_rn(y[j]);
        H0.b[j] = h;
        L0.b[j] = __float2bfloat16_rn(y[j] - __bfloat162float(h));
        __nv_bfloat16 h2 = __float2bfloat16_rn(y[4 + j]);
        H1.b[j] = h2;
        L1.b[j] = __float2bfloat16_rn(y[4 + j] - __bfloat162float(h2));
    }
    int c1 = lane * 4;
    int c2 = 128 + lane * 4;
    *(uint2*)(g_hhi + blk_idx(row, c1)) = H0.u;
    *(uint2*)(g_hhi + blk_idx(row, c2)) = H1.u;
    *(uint2*)(g_hlo + blk_idx(row, c1)) = L0.u;
    *(uint2*)(g_hlo + blk_idx(row, c2)) = L1.u;
}

// ---------------- segment starts from sorted b ----------------
__global__ void seg_starts(const int* __restrict__ b)
{
    int i = blockIdx.x * blockDim.x + threadIdx.x;
    if (i >= NN) return;
    int cur = b[i];
    if (i == 0) {
        for (int g = 0; g <= cur; g++) g_starts[g] = 0;
    } else {
        int prev = b[i - 1];
        if (prev != cur)
            for (int g = prev + 1; g <= cur; g++) g_starts[g] = i;
    }
    if (i == NN - 1)
        for (int g = cur + 1; g <= BBG; g++) g_starts[g] = NN;
}

// ---------------- readout: mean || max per graph ----------------
__global__ void readout_kernel(void)
{
    int g = blockIdx.x;
    int s = g_starts[g], en = g_starts[g + 1];
    int c = threadIdx.x;
    float sum = 0.f, mx = -INFINITY;
    for (int r = s; r < en; r++) {
        float v = g_h[(size_t)r * 256 + c];
        sum += v;
        mx = fmaxf(mx, v);
    }
    int   cnt   = en - s;
    float denom = (cnt > 0) ? (float)cnt : 1.f;
    g_gout[(size_t)g * 512 + c]       = sum / denom;
    g_gout[(size_t)g * 512 + 256 + c] = (cnt > 0) ? mx : 0.f;
}

// ---------------- FiLM + predictor, 8 graphs per block ----------------
__global__ __launch_bounds__(256)
void film_pred(const float* __restrict__ ctx, const int* __restrict__ pid,
               const float* __restrict__ gW1, const float* __restrict__ gb1,
               const float* __restrict__ glng, const float* __restrict__ glnb,
               const float* __restrict__ gW2, const float* __restrict__ gb2,
               const float* __restrict__ bW1, const float* __restrict__ bb1,
               const float* __restrict__ blng, const float* __restrict__ blnb,
               const float* __restrict__ bW2, const float* __restrict__ bb2,
               const float* __restrict__ pW1, const float* __restrict__ pb1,
               const float* __restrict__ pW2, const float* __restrict__ pb2,
               float* __restrict__ out)
{
    __shared__ float s_c[8][128];
    __shared__ float s_t[8][256];
    __shared__ float s_hmod[8][512];

    int tid = threadIdx.x;
    int g0  = blockIdx.x * 8;

    for (int i = tid; i < 8 * 128; i += 256) {
        int r = i >> 7, k = i & 127;
        s_c[r][k] = ctx[(size_t)pid[g0 + r] * 128 + k];
    }
    __syncthreads();

#pragma unroll
    for (int net = 0; net < 2; net++) {
        const float* W1 = net ? bW1 : gW1;
        const float* B1 = net ? bb1 : gb1;
        const float* LG = net ? blng : glng;
        const float* LB = net ? blnb : glnb;
        const float* W2 = net ? bW2 : gW2;
        const float* B2 = net ? bb2 : gb2;

        float a1[8];
#pragma unroll
        for (int r = 0; r < 8; r++) a1[r] = B1[tid];
        for (int k = 0; k < 128; k++) {
            float w = W1[k * 256 + tid];
#pragma unroll
            for (int r = 0; r < 8; r++) a1[r] += s_c[r][k] * w;
        }
#pragma unroll
        for (int r = 0; r < 8; r++) s_t[r][tid] = a1[r];
        __syncthreads();

        {
            int r = tid >> 5, lane = tid & 31;
            float x[8], s = 0.f, q = 0.f;
#pragma unroll
            for (int j = 0; j < 8; j++) {
                x[j] = s_t[r][lane + 32 * j];
                s += x[j]; q += x[j] * x[j];
            }
#pragma unroll
            for (int o = 16; o > 0; o >>= 1) {
                s += __shfl_xor_sync(0xFFFFFFFFu, s, o);
                q += __shfl_xor_sync(0xFFFFFFFFu, q, o);
            }
            float mu  = s * (1.f / 256.f);
            float var = q * (1.f / 256.f) - mu * mu;
            float rs  = rsqrtf(var + 1e-5f);
#pragma unroll
            for (int j = 0; j < 8; j++) {
                int cc = lane + 32 * j;
                float y = (x[j] - mu) * rs * LG[cc] + LB[cc];
                s_t[r][cc] = fmaxf(y, 0.f);
            }
        }
        __syncthreads();

        float a20[8], a21[8];
#pragma unroll
        for (int r = 0; r < 8; r++) { a20[r] = 0.f; a21[r] = 0.f; }
        for (int k = 0; k < 256; k++) {
            float w0 = W2[k * 512 + tid];
            float w1 = W2[k * 512 + tid + 256];
#pragma unroll
            for (int r = 0; r < 8; r++) {
                float t = s_t[r][k];
                a20[r] += t * w0;
                a21[r] += t * w1;
            }
        }
        float bc0 = B2[tid], bc1 = B2[tid + 256];
        if (net == 0) {
#pragma unroll
            for (int r = 0; r < 8; r++) {
                s_hmod[r][tid]       = (a20[r] + bc0) * g_gout[(size_t)(g0 + r) * 512 + tid];
                s_hmod[r][tid + 256] = (a21[r] + bc1) * g_gout[(size_t)(g0 + r) * 512 + tid + 256];
            }
        } else {
#pragma unroll
            for (int r = 0; r < 8; r++) {
                s_hmod[r][tid]       += a20[r] + bc0;
                s_hmod[r][tid + 256] += a21[r] + bc1;
            }
        }
        __syncthreads();
    }

    float az[8];
#pragma unroll
    for (int r = 0; r < 8; r++) az[r] = pb1[tid];
    for (int k = 0; k < 512; k++) {
        float w = pW1[k * 256 + tid];
#pragma unroll
        for (int r = 0; r < 8; r++) az[r] += s_hmod[r][k] * w;
    }
#pragma unroll
    for (int r = 0; r < 8; r++) s_t[r][tid] = fmaxf(az[r], 0.f);
    __syncthreads();

    {
        int r = tid >> 5, lane = tid & 31;
        float p = 0.f;
#pragma unroll
        for (int j = 0; j < 8; j++) {
            int cc = lane + 32 * j;
            p += s_t[r][cc] * pW2[cc];
        }
#pragma unroll
        for (int o = 16; o > 0; o >>= 1) p += __shfl_xor_sync(0xFFFFFFFFu, p, o);
        if (lane == 0) out[g0 + r] = p + pb2[0];
    }
}

// ---------------- host launcher ----------------
extern "C" void kernel_launch(void* const* d_in, const int* in_sizes, int n_in,
                              void* d_out, int out_size)
{
    (void)in_sizes; (void)n_in; (void)out_size;

    const float* nf   = (const float*)d_in[0];
    const int*   ei   = (const int*)  d_in[1];
    const float* ef   = (const float*)d_in[2];
    const int*   bseg = (const int*)  d_in[3];
    const int*   pid  = (const int*)  d_in[4];
    const float* Wn   = (const float*)d_in[5];
    const float* bn   = (const float*)d_in[6];
    const float* We   = (const float*)d_in[7];
    const float* be   = (const float*)d_in[8];
    const float* Wm   = (const float*)d_in[9];
    const float* bm   = (const float*)d_in[10];
    const float* Wu   = (const float*)d_in[11];
    const float* bu   = (const float*)d_in[12];
    const float* lng  = (const float*)d_in[13];
    const float* lnb  = (const float*)d_in[14];
    const float* ctx  = (const float*)d_in[15];
    const float* gW1  = (const float*)d_in[16];
    const float* gb1  = (const float*)d_in[17];
    const float* glng = (const float*)d_in[18];
    const float* glnb = (const float*)d_in[19];
    const float* gW2  = (const float*)d_in[20];
    const float* gb2  = (const float*)d_in[21];
    const float* bW1  = (const float*)d_in[22];
    const float* bb1  = (const float*)d_in[23];
    const float* blng = (const float*)d_in[24];
    const float* blnb = (const float*)d_in[25];
    const float* bW2  = (const float*)d_in[26];
    const float* bb2  = (const float*)d_in[27];
    const float* pW1  = (const float*)d_in[28];
    const float* pb1  = (const float*)d_in[29];
    const float* pW2  = (const float*)d_in[30];
    const float* pb2  = (const float*)d_in[31];
    float* out = (float*)d_out;

    const int* src = ei;
    const int* dst = ei + EE;

    float *h_ptr, *agg_ptr, *t_ptr;
    __nv_bfloat16 *hhi, *hlo, *ehi, *elo;
    uint4 *wPkHi, *wPkLo;
    cudaGetSymbolAddress((void**)&h_ptr,   g_h);
    cudaGetSymbolAddress((void**)&agg_ptr, g_agg);
    cudaGetSymbolAddress((void**)&t_ptr,   g_t);
    cudaGetSymbolAddress((void**)&hhi,     g_hhi);
    cudaGetSymbolAddress((void**)&hlo,     g_hlo);
    cudaGetSymbolAddress((void**)&ehi,     g_ehi);
    cudaGetSymbolAddress((void**)&elo,     g_elo);
    cudaGetSymbolAddress((void**)&wPkHi,   g_wPkHi);
    cudaGetSymbolAddress((void**)&wPkLo,   g_wPkLo);

    cudaFuncSetAttribute(mma_gemm<1, 2>, cudaFuncAttributeMaxDynamicSharedMemorySize, SM1);
    cudaFuncSetAttribute(mma_gemm<1, 3>, cudaFuncAttributeMaxDynamicSharedMemorySize, SM1);
    cudaFuncSetAttribute(mma_gemm<0, 4>, cudaFuncAttributeMaxDynamicSharedMemorySize, SM0);

    dim3 thr(256);

    // pack weights into B-fragment order (hi/lo)
    pack_weights<<<384, 256>>>(Wm, Wu);

    // input embeddings: h (fp32 + blocked bf16 split), e (blocked bf16 split only)
    gemm_emb<1><<<dim3(2, NN / 128), thr>>>(nf, 69, 69, Wn, bn, h_ptr, hhi, hlo);
    gemm_emb<2><<<dim3(2, EE / 128), thr>>>(ef, 9, 9, We, be, nullptr, ehi, elo);

    // MPNN layers
    for (int l = 0; l < LLAY; l++) {
        const uint4* topHi = wPkHi + (size_t)l * 8192;
        const uint4* topLo = wPkLo + (size_t)l * 8192;
        const uint4* botHi = wPkHi + (size_t)(4 + l) * 8192;
        const uint4* botLo = wPkLo + (size_t)(4 + l) * 8192;
        const uint4* wuHi  = wPkHi + (size_t)(8 + l) * 8192;
        const uint4* wuLo  = wPkLo + (size_t)(8 + l) * 8192;

        cudaMemsetAsync(agg_ptr, 0, (size_t)NN * HIDD * sizeof(float), 0);

        // t = h @ Wm_top
        mma_gemm<1, 2><<<dim3(2, NN / 128), thr, SM1>>>(
            nullptr, hhi, hlo, topHi, topLo, nullptr, t_ptr, nullptr, nullptr, nullptr);

        // agg[dst] += relu(e @ Wm_bot + bm + t[src])
        mma_gemm<1, 3><<<dim3(2, EE / 128), thr, SM1>>>(
            nullptr, ehi, elo, botHi, botLo, bm + (size_t)l * 256, agg_ptr, src, dst, t_ptr);

        // h = h + relu(agg @ Wu + bu)   (residual fused, in place)
        mma_gemm<0, 4><<<dim3(2, NN / 128), thr, SM0>>>(
            agg_ptr, nullptr, nullptr, wuHi, wuLo, bu + (size_t)l * 256, h_ptr,
            nullptr, nullptr, h_ptr);

        // h = LN(h) in place + refresh blocked bf16 split
        ln_kernel<<<NN / 8, 256>>>(lng + (size_t)l * 256, lnb + (size_t)l * 256);
    }

    // readout + FiLM + predictor
    seg_starts<<<NN / 256, 256>>>(bseg);
    readout_kernel<<<BBG, 256>>>();
    film_pred<<<BBG / 8, 256>>>(ctx, pid,
                                gW1, gb1, glng, glnb, gW2, gb2,
                                bW1, bb1, blng, blnb, bW2, bb2,
                                pW1, pb1, pW2, pb2, out);
}